// round 1
// baseline (speedup 1.0000x reference)
#include <cuda_runtime.h>
#include <math.h>

// ---------------------------------------------------------------------------
// Problem dims (fixed by the reference)
// ---------------------------------------------------------------------------
#define BATCH   2
#define SEQ     2048
#define TOK     (BATCH * SEQ)      // 4096 tokens
#define DIM     1024
#define HEADS   16
#define HD      64                 // head dim
#define HIDDEN  (4 * DIM)          // 4096
#define C3      (3 * DIM)          // 3072

// ---------------------------------------------------------------------------
// Scratch (static device globals — no allocations allowed)
// ---------------------------------------------------------------------------
__device__ float g_h1  [TOK * DIM];     // ln1(x)
__device__ float g_qkv [TOK * C3];      // h1 @ w_qkv
__device__ float g_attn[TOK * DIM];     // attention output (merged heads)
__device__ float g_x1  [TOK * DIM];     // x + attn@w_proj + b_proj
__device__ float g_h2  [TOK * DIM];     // ln2(x1)
__device__ float g_hid [TOK * HIDDEN];  // gelu(h2@w1+b1)

// ---------------------------------------------------------------------------
// LayerNorm: one block per token row of 1024, 256 threads x float4
// ---------------------------------------------------------------------------
__global__ void __launch_bounds__(256) ln_kernel(
    const float* __restrict__ x, const float* __restrict__ g,
    const float* __restrict__ b, float* __restrict__ out)
{
    const int row = blockIdx.x;
    const int tid = threadIdx.x;
    const float4* xr = reinterpret_cast<const float4*>(x + (long)row * DIM);
    float4 v = xr[tid];

    __shared__ float red1[8];
    __shared__ float red2[8];

    float s = v.x + v.y + v.z + v.w;
    #pragma unroll
    for (int off = 16; off; off >>= 1) s += __shfl_xor_sync(0xffffffffu, s, off);
    if ((tid & 31) == 0) red1[tid >> 5] = s;
    __syncthreads();
    float tot = 0.f;
    #pragma unroll
    for (int w = 0; w < 8; w++) tot += red1[w];
    const float mean = tot * (1.0f / DIM);

    float dx = v.x - mean, dy = v.y - mean, dz = v.z - mean, dw = v.w - mean;
    float q = dx * dx + dy * dy + dz * dz + dw * dw;
    #pragma unroll
    for (int off = 16; off; off >>= 1) q += __shfl_xor_sync(0xffffffffu, q, off);
    if ((tid & 31) == 0) red2[tid >> 5] = q;
    __syncthreads();
    float qtot = 0.f;
    #pragma unroll
    for (int w = 0; w < 8; w++) qtot += red2[w];
    const float rstd = rsqrtf(qtot * (1.0f / DIM) + 1e-5f);

    float4 gv = reinterpret_cast<const float4*>(g)[tid];
    float4 bv = reinterpret_cast<const float4*>(b)[tid];
    float4 o;
    o.x = dx * rstd * gv.x + bv.x;
    o.y = dy * rstd * gv.y + bv.y;
    o.z = dz * rstd * gv.z + bv.z;
    o.w = dw * rstd * gv.w + bv.w;
    reinterpret_cast<float4*>(out + (long)row * DIM)[tid] = o;
}

// ---------------------------------------------------------------------------
// SGEMM: C[M,N] = A[M,K] @ B[K,N] (+bias, +gelu, +residual per EPI bits)
// 128x128 block tile, BK=8, 256 threads, 8x8 per thread. All dims divide tiles.
// EPI: 1=bias(col), 2=gelu, 4=residual add
// ---------------------------------------------------------------------------
__device__ __forceinline__ float gelu_erf(float v) {
    return 0.5f * v * (1.0f + erff(v * 0.70710678118654752440f));
}

template <int EPI>
__global__ void __launch_bounds__(256) sgemm_kernel(
    const float* __restrict__ A, const float* __restrict__ B,
    const float* __restrict__ bias, const float* __restrict__ R,
    float* __restrict__ C, int M, int N, int K)
{
    const int BM = 128, BN = 128, BK = 8;
    __shared__ float As[BK][BM];
    __shared__ float Bs[BK][BN];

    const int tid = threadIdx.x;
    const int bm = blockIdx.y * BM;
    const int bn = blockIdx.x * BN;
    const int tx = tid & 15;         // 16 cols of threads
    const int ty = tid >> 4;         // 16 rows of threads

    // A tile load: each thread one float4 (row = tid/2, col = (tid&1)*4)
    const int arow = tid >> 1;
    const int acol = (tid & 1) << 2;
    // B tile load: each thread one float4 (row = tid/32, col = (tid&31)*4)
    const int brow = tid >> 5;
    const int bcol = (tid & 31) << 2;

    float acc[8][8];
    #pragma unroll
    for (int i = 0; i < 8; i++)
        #pragma unroll
        for (int j = 0; j < 8; j++) acc[i][j] = 0.f;

    const float* Aptr = A + (long)(bm + arow) * K + acol;
    const float* Bptr = B + (long)brow * N + bn + bcol;

    for (int k0 = 0; k0 < K; k0 += BK) {
        float4 a = *reinterpret_cast<const float4*>(Aptr + k0);
        As[acol + 0][arow] = a.x;
        As[acol + 1][arow] = a.y;
        As[acol + 2][arow] = a.z;
        As[acol + 3][arow] = a.w;
        float4 bvec = *reinterpret_cast<const float4*>(Bptr + (long)k0 * N);
        *reinterpret_cast<float4*>(&Bs[brow][bcol]) = bvec;
        __syncthreads();

        #pragma unroll
        for (int kk = 0; kk < BK; kk++) {
            float ar[8], br[8];
            *reinterpret_cast<float4*>(&ar[0]) = *reinterpret_cast<const float4*>(&As[kk][ty * 8]);
            *reinterpret_cast<float4*>(&ar[4]) = *reinterpret_cast<const float4*>(&As[kk][ty * 8 + 4]);
            *reinterpret_cast<float4*>(&br[0]) = *reinterpret_cast<const float4*>(&Bs[kk][tx * 8]);
            *reinterpret_cast<float4*>(&br[4]) = *reinterpret_cast<const float4*>(&Bs[kk][tx * 8 + 4]);
            #pragma unroll
            for (int i = 0; i < 8; i++)
                #pragma unroll
                for (int j = 0; j < 8; j++)
                    acc[i][j] = fmaf(ar[i], br[j], acc[i][j]);
        }
        __syncthreads();
    }

    #pragma unroll
    for (int i = 0; i < 8; i++) {
        const int r = bm + ty * 8 + i;
        #pragma unroll
        for (int j = 0; j < 8; j++) {
            const int c = bn + tx * 8 + j;
            float v = acc[i][j];
            if (EPI & 1) v += bias[c];
            if (EPI & 2) v = gelu_erf(v);
            if (EPI & 4) v += R[(long)r * N + c];
            C[(long)r * N + c] = v;
        }
    }
}

// ---------------------------------------------------------------------------
// Flash attention (fp32): one block per (batch*head, 64-query tile).
// 256 threads = 16x16; each thread owns a 4x4 sub-tile.
// K/V smem uses XOR swizzle (col = d ^ row) -> <=2-way bank conflicts.
// 48KB static smem exactly: Qs + KVs + Ps (64x64 fp32 each).
// ---------------------------------------------------------------------------
__global__ void __launch_bounds__(256) flash_kernel(
    const float* __restrict__ qkv, float* __restrict__ out)
{
    __shared__ float Qs[64 * 64];
    __shared__ float KVs[64 * 64];
    __shared__ float Ps[64 * 64];

    const int tid = threadIdx.x;
    const int tx = tid & 15;
    const int ty = tid >> 4;
    const int qt = blockIdx.x;          // 0..31
    const int bh = blockIdx.y;          // 0..31
    const int b  = bh >> 4;
    const int h  = bh & 15;
    const int q0 = qt * 64;

    const long base = ((long)b * SEQ) * C3 + h * HD;   // q part; k:+1024, v:+2048

    // Load Q tile, pre-scaled by hd^-0.5 = 0.125
    #pragma unroll
    for (int r = 0; r < 16; r++) {
        int idx = r * 256 + tid;
        int qi = idx >> 6, d = idx & 63;
        Qs[qi * 64 + d] = qkv[base + (long)(q0 + qi) * C3 + d] * 0.125f;
    }

    float O[4][4];
    float m[4], l[4];
    #pragma unroll
    for (int i = 0; i < 4; i++) {
        m[i] = -1e30f; l[i] = 0.f;
        #pragma unroll
        for (int j = 0; j < 4; j++) O[i][j] = 0.f;
    }

    for (int kt = 0; kt < SEQ / 64; kt++) {
        const int k0 = kt * 64;
        __syncthreads();   // prior-iteration readers of KVs/Ps done

        // Load K tile swizzled: element (kj,d) stored at kj*64 + (d^kj)
        #pragma unroll
        for (int r = 0; r < 16; r++) {
            int idx = r * 256 + tid;
            int kj = idx >> 6, d = idx & 63;
            KVs[kj * 64 + (d ^ kj)] = qkv[base + (long)(k0 + kj) * C3 + 1024 + d];
        }
        __syncthreads();

        // S = Q @ K^T (64x64x64)
        float s[4][4];
        #pragma unroll
        for (int i = 0; i < 4; i++)
            #pragma unroll
            for (int j = 0; j < 4; j++) s[i][j] = 0.f;

        #pragma unroll 4
        for (int k = 0; k < 64; k++) {
            float qr[4], kr[4];
            #pragma unroll
            for (int i = 0; i < 4; i++) qr[i] = Qs[(ty * 4 + i) * 64 + k];
            #pragma unroll
            for (int j = 0; j < 4; j++) {
                int kj = tx * 4 + j;
                kr[j] = KVs[kj * 64 + (k ^ kj)];
            }
            #pragma unroll
            for (int i = 0; i < 4; i++)
                #pragma unroll
                for (int j = 0; j < 4; j++)
                    s[i][j] = fmaf(qr[i], kr[j], s[i][j]);
        }

        // Online softmax per query row (row spread across 16 tx lanes)
        #pragma unroll
        for (int i = 0; i < 4; i++) {
            float tmax = fmaxf(fmaxf(s[i][0], s[i][1]), fmaxf(s[i][2], s[i][3]));
            #pragma unroll
            for (int off = 1; off < 16; off <<= 1)
                tmax = fmaxf(tmax, __shfl_xor_sync(0xffffffffu, tmax, off));
            const float newm = fmaxf(m[i], tmax);
            const float corr = __expf(m[i] - newm);
            float psum = 0.f;
            #pragma unroll
            for (int j = 0; j < 4; j++) {
                float p = __expf(s[i][j] - newm);
                s[i][j] = p;
                psum += p;
            }
            #pragma unroll
            for (int off = 1; off < 16; off <<= 1)
                psum += __shfl_xor_sync(0xffffffffu, psum, off);
            l[i] = l[i] * corr + psum;
            m[i] = newm;
            #pragma unroll
            for (int j = 0; j < 4; j++) O[i][j] *= corr;
            #pragma unroll
            for (int j = 0; j < 4; j++)
                Ps[(ty * 4 + i) * 64 + tx * 4 + j] = s[i][j];
        }
        __syncthreads();   // S-compute readers of K done, P written

        // Load V tile (same swizzle, reuse KVs)
        #pragma unroll
        for (int r = 0; r < 16; r++) {
            int idx = r * 256 + tid;
            int kj = idx >> 6, d = idx & 63;
            KVs[kj * 64 + (d ^ kj)] = qkv[base + (long)(k0 + kj) * C3 + 2048 + d];
        }
        __syncthreads();

        // O += P @ V (64x64x64)
        #pragma unroll 4
        for (int j = 0; j < 64; j++) {
            float pv[4], vr[4];
            #pragma unroll
            for (int i = 0; i < 4; i++) pv[i] = Ps[(ty * 4 + i) * 64 + j];
            #pragma unroll
            for (int jd = 0; jd < 4; jd++)
                vr[jd] = KVs[j * 64 + ((tx * 4 + jd) ^ j)];
            #pragma unroll
            for (int i = 0; i < 4; i++)
                #pragma unroll
                for (int jd = 0; jd < 4; jd++)
                    O[i][jd] = fmaf(pv[i], vr[jd], O[i][jd]);
        }
    }

    // Normalize + write merged-head output [TOK, DIM]
    #pragma unroll
    for (int i = 0; i < 4; i++) {
        const float inv = 1.0f / l[i];
        const long row = (long)b * SEQ + q0 + ty * 4 + i;
        #pragma unroll
        for (int jd = 0; jd < 4; jd++)
            out[row * DIM + h * HD + tx * 4 + jd] = O[i][jd] * inv;
    }
}

// ---------------------------------------------------------------------------
// Launch
// ---------------------------------------------------------------------------
extern "C" void kernel_launch(void* const* d_in, const int* in_sizes, int n_in,
                              void* d_out, int out_size)
{
    const float* x      = (const float*)d_in[0];
    const float* ln1_g  = (const float*)d_in[1];
    const float* ln1_b  = (const float*)d_in[2];
    const float* w_qkv  = (const float*)d_in[3];
    const float* w_proj = (const float*)d_in[4];
    const float* b_proj = (const float*)d_in[5];
    const float* ln2_g  = (const float*)d_in[6];
    const float* ln2_b  = (const float*)d_in[7];
    const float* w1     = (const float*)d_in[8];
    const float* b1     = (const float*)d_in[9];
    const float* w2     = (const float*)d_in[10];
    const float* b2     = (const float*)d_in[11];
    float* out = (float*)d_out;

    float *h1, *qkv, *attn, *x1, *h2, *hid;
    cudaGetSymbolAddress((void**)&h1,   g_h1);
    cudaGetSymbolAddress((void**)&qkv,  g_qkv);
    cudaGetSymbolAddress((void**)&attn, g_attn);
    cudaGetSymbolAddress((void**)&x1,   g_x1);
    cudaGetSymbolAddress((void**)&h2,   g_h2);
    cudaGetSymbolAddress((void**)&hid,  g_hid);

    // 1) h1 = LN1(x)
    ln_kernel<<<TOK, 256>>>(x, ln1_g, ln1_b, h1);

    // 2) qkv = h1 @ w_qkv    [4096,3072]
    sgemm_kernel<0><<<dim3(C3 / 128, TOK / 128), 256>>>(
        h1, w_qkv, nullptr, nullptr, qkv, TOK, C3, DIM);

    // 3) attention
    flash_kernel<<<dim3(SEQ / 64, BATCH * HEADS), 256>>>(qkv, attn);

    // 4) x1 = x + attn @ w_proj + b_proj   (EPI: bias|residual = 5)
    sgemm_kernel<5><<<dim3(DIM / 128, TOK / 128), 256>>>(
        attn, w_proj, b_proj, x, x1, TOK, DIM, DIM);

    // 5) h2 = LN2(x1)
    ln_kernel<<<TOK, 256>>>(x1, ln2_g, ln2_b, h2);

    // 6) hid = gelu(h2 @ w1 + b1)   (EPI: bias|gelu = 3)
    sgemm_kernel<3><<<dim3(HIDDEN / 128, TOK / 128), 256>>>(
        h2, w1, b1, nullptr, hid, TOK, HIDDEN, DIM);

    // 7) out = x1 + hid @ w2 + b2   (EPI: bias|residual = 5)
    sgemm_kernel<5><<<dim3(DIM / 128, TOK / 128), 256>>>(
        hid, w2, b2, x1, out, TOK, DIM, HIDDEN);
}

// round 3
// speedup vs baseline: 1.6598x; 1.6598x over previous
#include <cuda_runtime.h>
#include <cstdint>
#include <math.h>

// ---------------------------------------------------------------------------
// Problem dims
// ---------------------------------------------------------------------------
#define BATCH   2
#define SEQ     2048
#define TOK     (BATCH * SEQ)      // 4096
#define DIM     1024
#define HEADS   16
#define HD      64
#define HIDDEN  (4 * DIM)          // 4096
#define C3      (3 * DIM)          // 3072

// ---------------------------------------------------------------------------
// Scratch (device globals; no allocations allowed)
// ---------------------------------------------------------------------------
__device__ float g_h1  [TOK * DIM];
__device__ float g_qkv [TOK * C3];
__device__ float g_attn[TOK * DIM];
__device__ float g_x1  [TOK * DIM];
__device__ float g_h2  [TOK * DIM];
__device__ float g_hid [TOK * HIDDEN];

__device__ __forceinline__ float to_tf32(float x) {
    float y; asm("cvt.rna.tf32.f32 %0, %1;" : "=f"(y) : "f"(x)); return y;
}
__device__ __forceinline__ float gelu_erf(float v) {
    return 0.5f * v * (1.0f + erff(v * 0.70710678118654752440f));
}

// mma.sync m16n8k8 tf32: D = A@B + C (fp32 accum)
__device__ __forceinline__ void mma_tf32(
    float& d0, float& d1, float& d2, float& d3,
    uint32_t a0, uint32_t a1, uint32_t a2, uint32_t a3,
    uint32_t b0, uint32_t b1)
{
    asm volatile(
        "mma.sync.aligned.m16n8k8.row.col.f32.tf32.tf32.f32 "
        "{%0,%1,%2,%3}, {%4,%5,%6,%7}, {%8,%9}, {%0,%1,%2,%3};"
        : "+f"(d0), "+f"(d1), "+f"(d2), "+f"(d3)
        : "r"(a0), "r"(a1), "r"(a2), "r"(a3), "r"(b0), "r"(b1));
}

// ---------------------------------------------------------------------------
// tf32 tensor-core GEMM: C[M,N] = A[M,K] @ B[K,N]  (B row-major, no transpose)
// CTA tile 128x128, BK=16, 256 threads = 8 warps (2x4), warp tile 64x32.
// Smem padded stride 136 -> conflict-free fragment loads.
// EPI bits: 1=bias, 2=gelu, 4=residual
// ---------------------------------------------------------------------------
#define LDP 136

template <int EPI>
__global__ void __launch_bounds__(256) mma_gemm(
    const float* __restrict__ A, const float* __restrict__ B,
    const float* __restrict__ bias, const float* __restrict__ R,
    float* __restrict__ C, int M, int N, int K)
{
    __shared__ float As[2][16][LDP];   // [k][m]
    __shared__ float Bs[2][16][LDP];   // [k][n]

    const int tid  = threadIdx.x;
    const int lane = tid & 31;
    const int warp = tid >> 5;
    const int wy = warp >> 2;          // 0..1  (m)
    const int wx = warp & 3;           // 0..3  (n)
    const int g  = lane >> 2;          // 0..7
    const int t  = lane & 3;           // 0..3
    const int bm = blockIdx.y * 128;
    const int bn = blockIdx.x * 128;

    // LDG assignments
    const int a_row = tid >> 1;              // 0..127
    const int a_col = (tid & 1) * 8;         // 0 or 8
    const int b_row = tid >> 4;              // 0..15
    const int b_col = (tid & 15) * 8;        // 0..120

    const float* Ag = A + (long)(bm + a_row) * K + a_col;
    const float* Bg = B + (long)b_row * N + bn + b_col;

    float acc[4][4][4];
    #pragma unroll
    for (int i = 0; i < 4; i++)
        #pragma unroll
        for (int j = 0; j < 4; j++)
            #pragma unroll
            for (int e = 0; e < 4; e++) acc[i][j][e] = 0.f;

    float ra[8], rb[8];
    // prologue: load tile 0
    {
        float4 v0 = *reinterpret_cast<const float4*>(Ag);
        float4 v1 = *reinterpret_cast<const float4*>(Ag + 4);
        ra[0]=v0.x; ra[1]=v0.y; ra[2]=v0.z; ra[3]=v0.w;
        ra[4]=v1.x; ra[5]=v1.y; ra[6]=v1.z; ra[7]=v1.w;
        float4 w0 = *reinterpret_cast<const float4*>(Bg);
        float4 w1 = *reinterpret_cast<const float4*>(Bg + 4);
        rb[0]=w0.x; rb[1]=w0.y; rb[2]=w0.z; rb[3]=w0.w;
        rb[4]=w1.x; rb[5]=w1.y; rb[6]=w1.z; rb[7]=w1.w;
    }
    // STS tile 0 (tf32-rounded)
    #pragma unroll
    for (int j = 0; j < 8; j++) As[0][a_col + j][a_row] = to_tf32(ra[j]);
    #pragma unroll
    for (int j = 0; j < 8; j++) Bs[0][b_row][b_col + j] = to_tf32(rb[j]);
    __syncthreads();

    const int NK = K >> 4;
    for (int it = 0; it < NK; ++it) {
        const int buf = it & 1;
        // prefetch next tile
        if (it + 1 < NK) {
            const int k0 = (it + 1) << 4;
            float4 v0 = *reinterpret_cast<const float4*>(Ag + k0);
            float4 v1 = *reinterpret_cast<const float4*>(Ag + k0 + 4);
            ra[0]=v0.x; ra[1]=v0.y; ra[2]=v0.z; ra[3]=v0.w;
            ra[4]=v1.x; ra[5]=v1.y; ra[6]=v1.z; ra[7]=v1.w;
            float4 w0 = *reinterpret_cast<const float4*>(Bg + (long)k0 * N);
            float4 w1 = *reinterpret_cast<const float4*>(Bg + (long)k0 * N + 4);
            rb[0]=w0.x; rb[1]=w0.y; rb[2]=w0.z; rb[3]=w0.w;
            rb[4]=w1.x; rb[5]=w1.y; rb[6]=w1.z; rb[7]=w1.w;
        }
        // compute on buf
        #pragma unroll
        for (int ks = 0; ks < 2; ks++) {
            const int k8 = ks * 8;
            uint32_t af[4][4], bf[4][2];
            #pragma unroll
            for (int mf = 0; mf < 4; mf++) {
                const int m0 = wy * 64 + mf * 16;
                af[mf][0] = __float_as_uint(As[buf][k8 + t    ][m0 + g    ]);
                af[mf][1] = __float_as_uint(As[buf][k8 + t    ][m0 + g + 8]);
                af[mf][2] = __float_as_uint(As[buf][k8 + t + 4][m0 + g    ]);
                af[mf][3] = __float_as_uint(As[buf][k8 + t + 4][m0 + g + 8]);
            }
            #pragma unroll
            for (int nf = 0; nf < 4; nf++) {
                const int n0 = wx * 32 + nf * 8;
                bf[nf][0] = __float_as_uint(Bs[buf][k8 + t    ][n0 + g]);
                bf[nf][1] = __float_as_uint(Bs[buf][k8 + t + 4][n0 + g]);
            }
            #pragma unroll
            for (int mf = 0; mf < 4; mf++)
                #pragma unroll
                for (int nf = 0; nf < 4; nf++)
                    mma_tf32(acc[mf][nf][0], acc[mf][nf][1],
                             acc[mf][nf][2], acc[mf][nf][3],
                             af[mf][0], af[mf][1], af[mf][2], af[mf][3],
                             bf[nf][0], bf[nf][1]);
        }
        // stage next tile
        if (it + 1 < NK) {
            const int nb = buf ^ 1;
            #pragma unroll
            for (int j = 0; j < 8; j++) As[nb][a_col + j][a_row] = to_tf32(ra[j]);
            #pragma unroll
            for (int j = 0; j < 8; j++) Bs[nb][b_row][b_col + j] = to_tf32(rb[j]);
        }
        __syncthreads();
    }

    // Epilogue (documented c-frag layout: c0,c1 @ (row, col..col+1); c2,c3 @ row+8)
    #pragma unroll
    for (int mf = 0; mf < 4; mf++) {
        const long row = bm + wy * 64 + mf * 16 + g;
        #pragma unroll
        for (int nf = 0; nf < 4; nf++) {
            const long col = bn + wx * 32 + nf * 8 + t * 2;
            float2 v0 = make_float2(acc[mf][nf][0], acc[mf][nf][1]);
            float2 v1 = make_float2(acc[mf][nf][2], acc[mf][nf][3]);
            if (EPI & 1) {
                const float2 bv = *reinterpret_cast<const float2*>(bias + col);
                v0.x += bv.x; v0.y += bv.y;
                v1.x += bv.x; v1.y += bv.y;
            }
            if (EPI & 2) {
                v0.x = gelu_erf(v0.x); v0.y = gelu_erf(v0.y);
                v1.x = gelu_erf(v1.x); v1.y = gelu_erf(v1.y);
            }
            if (EPI & 4) {
                const float2 r0 = *reinterpret_cast<const float2*>(R + row * N + col);
                const float2 r1 = *reinterpret_cast<const float2*>(R + (row + 8) * N + col);
                v0.x += r0.x; v0.y += r0.y;
                v1.x += r1.x; v1.y += r1.y;
            }
            *reinterpret_cast<float2*>(C + row * N + col) = v0;
            *reinterpret_cast<float2*>(C + (row + 8) * N + col) = v1;
        }
    }
}

// ---------------------------------------------------------------------------
// LayerNorm
// ---------------------------------------------------------------------------
__global__ void __launch_bounds__(256) ln_kernel(
    const float* __restrict__ x, const float* __restrict__ g,
    const float* __restrict__ b, float* __restrict__ out)
{
    const int row = blockIdx.x;
    const int tid = threadIdx.x;
    const float4* xr = reinterpret_cast<const float4*>(x + (long)row * DIM);
    float4 v = xr[tid];

    __shared__ float red1[8];
    __shared__ float red2[8];

    float s = v.x + v.y + v.z + v.w;
    #pragma unroll
    for (int off = 16; off; off >>= 1) s += __shfl_xor_sync(0xffffffffu, s, off);
    if ((tid & 31) == 0) red1[tid >> 5] = s;
    __syncthreads();
    float tot = 0.f;
    #pragma unroll
    for (int w = 0; w < 8; w++) tot += red1[w];
    const float mean = tot * (1.0f / DIM);

    float dx = v.x - mean, dy = v.y - mean, dz = v.z - mean, dw = v.w - mean;
    float q = dx * dx + dy * dy + dz * dz + dw * dw;
    #pragma unroll
    for (int off = 16; off; off >>= 1) q += __shfl_xor_sync(0xffffffffu, q, off);
    if ((tid & 31) == 0) red2[tid >> 5] = q;
    __syncthreads();
    float qtot = 0.f;
    #pragma unroll
    for (int w = 0; w < 8; w++) qtot += red2[w];
    const float rstd = rsqrtf(qtot * (1.0f / DIM) + 1e-5f);

    float4 gv = reinterpret_cast<const float4*>(g)[tid];
    float4 bv = reinterpret_cast<const float4*>(b)[tid];
    float4 o;
    o.x = dx * rstd * gv.x + bv.x;
    o.y = dy * rstd * gv.y + bv.y;
    o.z = dz * rstd * gv.z + bv.z;
    o.w = dw * rstd * gv.w + bv.w;
    reinterpret_cast<float4*>(out + (long)row * DIM)[tid] = o;
}

// ---------------------------------------------------------------------------
// Flash attention fp32 SIMT (unchanged)
// ---------------------------------------------------------------------------
__global__ void __launch_bounds__(256) flash_kernel(
    const float* __restrict__ qkv, float* __restrict__ out)
{
    __shared__ float Qs[64 * 64];
    __shared__ float KVs[64 * 64];
    __shared__ float Ps[64 * 64];

    const int tid = threadIdx.x;
    const int tx = tid & 15;
    const int ty = tid >> 4;
    const int qt = blockIdx.x;
    const int bh = blockIdx.y;
    const int b  = bh >> 4;
    const int h  = bh & 15;
    const int q0 = qt * 64;

    const long base = ((long)b * SEQ) * C3 + h * HD;

    #pragma unroll
    for (int r = 0; r < 16; r++) {
        int idx = r * 256 + tid;
        int qi = idx >> 6, d = idx & 63;
        Qs[qi * 64 + d] = qkv[base + (long)(q0 + qi) * C3 + d] * 0.125f;
    }

    float O[4][4];
    float m[4], l[4];
    #pragma unroll
    for (int i = 0; i < 4; i++) {
        m[i] = -1e30f; l[i] = 0.f;
        #pragma unroll
        for (int j = 0; j < 4; j++) O[i][j] = 0.f;
    }

    for (int kt = 0; kt < SEQ / 64; kt++) {
        const int k0 = kt * 64;
        __syncthreads();

        #pragma unroll
        for (int r = 0; r < 16; r++) {
            int idx = r * 256 + tid;
            int kj = idx >> 6, d = idx & 63;
            KVs[kj * 64 + (d ^ kj)] = qkv[base + (long)(k0 + kj) * C3 + 1024 + d];
        }
        __syncthreads();

        float s[4][4];
        #pragma unroll
        for (int i = 0; i < 4; i++)
            #pragma unroll
            for (int j = 0; j < 4; j++) s[i][j] = 0.f;

        #pragma unroll 4
        for (int k = 0; k < 64; k++) {
            float qr[4], kr[4];
            #pragma unroll
            for (int i = 0; i < 4; i++) qr[i] = Qs[(ty * 4 + i) * 64 + k];
            #pragma unroll
            for (int j = 0; j < 4; j++) {
                int kj = tx * 4 + j;
                kr[j] = KVs[kj * 64 + (k ^ kj)];
            }
            #pragma unroll
            for (int i = 0; i < 4; i++)
                #pragma unroll
                for (int j = 0; j < 4; j++)
                    s[i][j] = fmaf(qr[i], kr[j], s[i][j]);
        }

        #pragma unroll
        for (int i = 0; i < 4; i++) {
            float tmax = fmaxf(fmaxf(s[i][0], s[i][1]), fmaxf(s[i][2], s[i][3]));
            #pragma unroll
            for (int off = 1; off < 16; off <<= 1)
                tmax = fmaxf(tmax, __shfl_xor_sync(0xffffffffu, tmax, off));
            const float newm = fmaxf(m[i], tmax);
            const float corr = __expf(m[i] - newm);
            float psum = 0.f;
            #pragma unroll
            for (int j = 0; j < 4; j++) {
                float p = __expf(s[i][j] - newm);
                s[i][j] = p;
                psum += p;
            }
            #pragma unroll
            for (int off = 1; off < 16; off <<= 1)
                psum += __shfl_xor_sync(0xffffffffu, psum, off);
            l[i] = l[i] * corr + psum;
            m[i] = newm;
            #pragma unroll
            for (int j = 0; j < 4; j++) O[i][j] *= corr;
            #pragma unroll
            for (int j = 0; j < 4; j++)
                Ps[(ty * 4 + i) * 64 + tx * 4 + j] = s[i][j];
        }
        __syncthreads();

        #pragma unroll
        for (int r = 0; r < 16; r++) {
            int idx = r * 256 + tid;
            int kj = idx >> 6, d = idx & 63;
            KVs[kj * 64 + (d ^ kj)] = qkv[base + (long)(k0 + kj) * C3 + 2048 + d];
        }
        __syncthreads();

        #pragma unroll 4
        for (int j = 0; j < 64; j++) {
            float pv[4], vr[4];
            #pragma unroll
            for (int i = 0; i < 4; i++) pv[i] = Ps[(ty * 4 + i) * 64 + j];
            #pragma unroll
            for (int jd = 0; jd < 4; jd++)
                vr[jd] = KVs[j * 64 + ((tx * 4 + jd) ^ j)];
            #pragma unroll
            for (int i = 0; i < 4; i++)
                #pragma unroll
                for (int jd = 0; jd < 4; jd++)
                    O[i][jd] = fmaf(pv[i], vr[jd], O[i][jd]);
        }
    }

    #pragma unroll
    for (int i = 0; i < 4; i++) {
        const float inv = 1.0f / l[i];
        const long row = (long)b * SEQ + q0 + ty * 4 + i;
        #pragma unroll
        for (int jd = 0; jd < 4; jd++)
            out[row * DIM + h * HD + tx * 4 + jd] = O[i][jd] * inv;
    }
}

// ---------------------------------------------------------------------------
// Launch
// ---------------------------------------------------------------------------
extern "C" void kernel_launch(void* const* d_in, const int* in_sizes, int n_in,
                              void* d_out, int out_size)
{
    const float* x      = (const float*)d_in[0];
    const float* ln1_g  = (const float*)d_in[1];
    const float* ln1_b  = (const float*)d_in[2];
    const float* w_qkv  = (const float*)d_in[3];
    const float* w_proj = (const float*)d_in[4];
    const float* b_proj = (const float*)d_in[5];
    const float* ln2_g  = (const float*)d_in[6];
    const float* ln2_b  = (const float*)d_in[7];
    const float* w1     = (const float*)d_in[8];
    const float* b1     = (const float*)d_in[9];
    const float* w2     = (const float*)d_in[10];
    const float* b2     = (const float*)d_in[11];
    float* out = (float*)d_out;

    float *h1, *qkv, *attn, *x1, *h2, *hid;
    cudaGetSymbolAddress((void**)&h1,   g_h1);
    cudaGetSymbolAddress((void**)&qkv,  g_qkv);
    cudaGetSymbolAddress((void**)&attn, g_attn);
    cudaGetSymbolAddress((void**)&x1,   g_x1);
    cudaGetSymbolAddress((void**)&h2,   g_h2);
    cudaGetSymbolAddress((void**)&hid,  g_hid);

    // 1) h1 = LN1(x)
    ln_kernel<<<TOK, 256>>>(x, ln1_g, ln1_b, h1);

    // 2) qkv = h1 @ w_qkv
    mma_gemm<0><<<dim3(C3 / 128, TOK / 128), 256>>>(
        h1, w_qkv, nullptr, nullptr, qkv, TOK, C3, DIM);

    // 3) attention
    flash_kernel<<<dim3(SEQ / 64, BATCH * HEADS), 256>>>(qkv, attn);

    // 4) x1 = x + attn @ w_proj + b_proj
    mma_gemm<5><<<dim3(DIM / 128, TOK / 128), 256>>>(
        attn, w_proj, b_proj, x, x1, TOK, DIM, DIM);

    // 5) h2 = LN2(x1)
    ln_kernel<<<TOK, 256>>>(x1, ln2_g, ln2_b, h2);

    // 6) hid = gelu(h2 @ w1 + b1)
    mma_gemm<3><<<dim3(HIDDEN / 128, TOK / 128), 256>>>(
        h2, w1, b1, nullptr, hid, TOK, HIDDEN, DIM);

    // 7) out = x1 + hid @ w2 + b2
    mma_gemm<5><<<dim3(DIM / 128, TOK / 128), 256>>>(
        hid, w2, b2, x1, out, TOK, DIM, HIDDEN);
}

// round 4
// speedup vs baseline: 3.8527x; 2.3212x over previous
#include <cuda_runtime.h>
#include <cstdint>
#include <math.h>

// ---------------------------------------------------------------------------
// Problem dims
// ---------------------------------------------------------------------------
#define BATCH   2
#define SEQ     2048
#define TOK     (BATCH * SEQ)      // 4096
#define DIM     1024
#define HEADS   16
#define HD      64
#define HIDDEN  (4 * DIM)          // 4096
#define C3      (3 * DIM)          // 3072

// ---------------------------------------------------------------------------
// Scratch (device globals; no allocations allowed)
// ---------------------------------------------------------------------------
__device__ float g_h1  [TOK * DIM];
__device__ float g_qkv [TOK * C3];
__device__ float g_attn[TOK * DIM];
__device__ float g_x1  [TOK * DIM];
__device__ float g_h2  [TOK * DIM];
__device__ float g_hid [TOK * HIDDEN];
// tf32-rounded weight copies
__device__ float g_wqkv [DIM * C3];
__device__ float g_wproj[DIM * DIM];
__device__ float g_w1   [DIM * HIDDEN];
__device__ float g_w2   [HIDDEN * DIM];

// ---------------------------------------------------------------------------
// Helpers
// ---------------------------------------------------------------------------
__device__ __forceinline__ uint32_t smem_u32(const void* p) {
    uint32_t a;
    asm("{ .reg .u64 t; cvta.to.shared.u64 t, %1; cvt.u32.u64 %0, t; }" : "=r"(a) : "l"(p));
    return a;
}
__device__ __forceinline__ float to_tf32(float x) {
    float y; asm("cvt.rna.tf32.f32 %0, %1;" : "=f"(y) : "f"(x)); return y;
}
__device__ __forceinline__ float gelu_erf(float v) {
    return 0.5f * v * (1.0f + erff(v * 0.70710678118654752440f));
}
__device__ __forceinline__ void mma_tf32(
    float& d0, float& d1, float& d2, float& d3,
    uint32_t a0, uint32_t a1, uint32_t a2, uint32_t a3,
    uint32_t b0, uint32_t b1)
{
    asm volatile(
        "mma.sync.aligned.m16n8k8.row.col.f32.tf32.tf32.f32 "
        "{%0,%1,%2,%3}, {%4,%5,%6,%7}, {%8,%9}, {%0,%1,%2,%3};"
        : "+f"(d0), "+f"(d1), "+f"(d2), "+f"(d3)
        : "r"(a0), "r"(a1), "r"(a2), "r"(a3), "r"(b0), "r"(b1));
}
__device__ __forceinline__ void cp_async16(uint32_t dst, const void* src) {
    asm volatile("cp.async.cg.shared.global [%0], [%1], 16;" :: "r"(dst), "l"(src));
}
#define CP_COMMIT asm volatile("cp.async.commit_group;")
template <int N>
__device__ __forceinline__ void cp_wait() {
    asm volatile("cp.async.wait_group %0;" :: "n"(N));
}

// ---------------------------------------------------------------------------
// tf32 tensor-core GEMM: C[M,N] = A[M,K] @ B[K,N], A/B pre-rounded to tf32.
// 128x128 tile, BK=32, 3-stage cp.async pipeline, 256 threads (8 warps 2x4).
// EPI bits: 1=bias, 2=gelu, 4=residual.  RND: round output to tf32 (rna).
// ---------------------------------------------------------------------------
#define AS_ST 36
#define BS_ST 136
#define AS_FL (128 * AS_ST)   // 4608 floats / stage
#define BS_FL (32 * BS_ST)    // 4352 floats / stage
#define GEMM_SMEM ((3 * AS_FL + 3 * BS_FL) * 4)  // 107520 bytes

template <int EPI, int RND>
__global__ void __launch_bounds__(256, 2) mma_gemm(
    const float* __restrict__ A, const float* __restrict__ B,
    const float* __restrict__ bias, const float* __restrict__ R,
    float* __restrict__ C, int M, int N, int K)
{
    extern __shared__ float sm[];
    float* Asm = sm;
    float* Bsm = sm + 3 * AS_FL;
    const uint32_t a_u32 = smem_u32(Asm);
    const uint32_t b_u32 = smem_u32(Bsm);

    const int tid = threadIdx.x;
    const int lane = tid & 31, warp = tid >> 5;
    const int wy = warp >> 2, wx = warp & 3;
    const int g = lane >> 2, t = lane & 3;
    const int bm = blockIdx.y * 128, bn = blockIdx.x * 128;

    auto issue = [&](int s, int k0) {
        #pragma unroll
        for (int w = 0; w < 4; w++) {
            int id = w * 256 + tid;
            int r = id >> 3, c = (id & 7) << 2;
            cp_async16(a_u32 + (uint32_t)(s * AS_FL + r * AS_ST + c) * 4,
                       A + (long)(bm + r) * K + k0 + c);
        }
        #pragma unroll
        for (int w = 0; w < 4; w++) {
            int id = w * 256 + tid;
            int r = id >> 5, c = (id & 31) << 2;
            cp_async16(b_u32 + (uint32_t)(s * BS_FL + r * BS_ST + c) * 4,
                       B + (long)(k0 + r) * N + bn + c);
        }
        CP_COMMIT;
    };

    float acc[4][4][4];
    #pragma unroll
    for (int i = 0; i < 4; i++)
        #pragma unroll
        for (int j = 0; j < 4; j++)
            #pragma unroll
            for (int e = 0; e < 4; e++) acc[i][j][e] = 0.f;

    const int NK = K >> 5;
    issue(0, 0);
    issue(1, 32);

    for (int it = 0; it < NK; ++it) {
        if (it == NK - 1) { cp_wait<0>(); } else { cp_wait<1>(); }
        __syncthreads();
        if (it + 2 < NK) issue((it + 2) % 3, (it + 2) << 5);

        const float* as = Asm + (it % 3) * AS_FL;
        const float* bs = Bsm + (it % 3) * BS_FL;
        #pragma unroll
        for (int k8 = 0; k8 < 32; k8 += 8) {
            uint32_t af[4][4], bf[4][2];
            #pragma unroll
            for (int mf = 0; mf < 4; mf++) {
                const int m0 = wy * 64 + mf * 16;
                af[mf][0] = __float_as_uint(as[(m0 + g)     * AS_ST + k8 + t]);
                af[mf][1] = __float_as_uint(as[(m0 + g + 8) * AS_ST + k8 + t]);
                af[mf][2] = __float_as_uint(as[(m0 + g)     * AS_ST + k8 + t + 4]);
                af[mf][3] = __float_as_uint(as[(m0 + g + 8) * AS_ST + k8 + t + 4]);
            }
            #pragma unroll
            for (int nf = 0; nf < 4; nf++) {
                const int n0 = wx * 32 + nf * 8;
                bf[nf][0] = __float_as_uint(bs[(k8 + t)     * BS_ST + n0 + g]);
                bf[nf][1] = __float_as_uint(bs[(k8 + t + 4) * BS_ST + n0 + g]);
            }
            #pragma unroll
            for (int mf = 0; mf < 4; mf++)
                #pragma unroll
                for (int nf = 0; nf < 4; nf++)
                    mma_tf32(acc[mf][nf][0], acc[mf][nf][1],
                             acc[mf][nf][2], acc[mf][nf][3],
                             af[mf][0], af[mf][1], af[mf][2], af[mf][3],
                             bf[nf][0], bf[nf][1]);
        }
    }

    // Epilogue
    #pragma unroll
    for (int mf = 0; mf < 4; mf++) {
        const long row = bm + wy * 64 + mf * 16 + g;
        #pragma unroll
        for (int nf = 0; nf < 4; nf++) {
            const long col = bn + wx * 32 + nf * 8 + t * 2;
            float2 v0 = make_float2(acc[mf][nf][0], acc[mf][nf][1]);
            float2 v1 = make_float2(acc[mf][nf][2], acc[mf][nf][3]);
            if (EPI & 1) {
                const float2 bv = *reinterpret_cast<const float2*>(bias + col);
                v0.x += bv.x; v0.y += bv.y;
                v1.x += bv.x; v1.y += bv.y;
            }
            if (EPI & 2) {
                v0.x = gelu_erf(v0.x); v0.y = gelu_erf(v0.y);
                v1.x = gelu_erf(v1.x); v1.y = gelu_erf(v1.y);
            }
            if (EPI & 4) {
                const float2 r0 = *reinterpret_cast<const float2*>(R + row * N + col);
                const float2 r1 = *reinterpret_cast<const float2*>(R + (row + 8) * N + col);
                v0.x += r0.x; v0.y += r0.y;
                v1.x += r1.x; v1.y += r1.y;
            }
            if (RND) {
                v0.x = to_tf32(v0.x); v0.y = to_tf32(v0.y);
                v1.x = to_tf32(v1.x); v1.y = to_tf32(v1.y);
            }
            *reinterpret_cast<float2*>(C + row * N + col) = v0;
            *reinterpret_cast<float2*>(C + (row + 8) * N + col) = v1;
        }
    }
}

// ---------------------------------------------------------------------------
// Flash attention, tf32 mma. CTA: 128 q-rows x 8 warps (16 rows each).
// K/V tiles of 64 keys via cp.async (V prefetched under S-matmul).
// exp2-domain softmax: Q pre-scaled by 0.125*log2(e).
// ---------------------------------------------------------------------------
#define FW  68
#define FWV 72
#define FQ_OFF 0
#define FP_OFF (128 * FW)                 // 8704
#define FK_OFF (2 * 128 * FW)             // 17408
#define FV_OFF (FK_OFF + 64 * FW)         // 21760
#define FLASH_SMEM ((FV_OFF + 64 * FWV) * 4)   // (21760+4608)*4 = 105472

__global__ void __launch_bounds__(256, 2) flash_mma(
    const float* __restrict__ qkv, float* __restrict__ out)
{
    extern __shared__ float sm[];
    float* Qs = sm + FQ_OFF;
    float* Ps = sm + FP_OFF;
    float* Ks = sm + FK_OFF;
    float* Vs = sm + FV_OFF;
    const uint32_t k_u32 = smem_u32(Ks);
    const uint32_t v_u32 = smem_u32(Vs);

    const int tid = threadIdx.x;
    const int lane = tid & 31, warp = tid >> 5;
    const int g = lane >> 2, t = lane & 3;
    const int b = blockIdx.y >> 4, h = blockIdx.y & 15;
    const int q0 = blockIdx.x * 128;
    const int m0 = warp * 16;
    const long base = (long)b * SEQ * C3 + h * HD;

    // Load Q tile, scale by 0.125*log2(e), rna-round to tf32
    const float qscale = 0.125f * 1.4426950408889634f;
    #pragma unroll
    for (int i = 0; i < 8; i++) {
        int id = i * 256 + tid;
        int r = id >> 4, c = (id & 15) << 2;
        float4 v = *reinterpret_cast<const float4*>(qkv + base + (long)(q0 + r) * C3 + c);
        v.x = to_tf32(v.x * qscale); v.y = to_tf32(v.y * qscale);
        v.z = to_tf32(v.z * qscale); v.w = to_tf32(v.w * qscale);
        *reinterpret_cast<float4*>(Qs + r * FW + c) = v;
    }

    float Of[8][4];
    #pragma unroll
    for (int nf = 0; nf < 8; nf++)
        #pragma unroll
        for (int e = 0; e < 4; e++) Of[nf][e] = 0.f;
    float m_[2] = {-1e30f, -1e30f};
    float l_[2] = {0.f, 0.f};

    const int NT = SEQ / 64;
    for (int kt = 0; kt < NT; kt++) {
        const long kb = base + (long)(kt * 64) * C3;
        __syncthreads();     // Q visible (kt=0); prev tile's Ks/Vs readers done

        // issue K tile, then V tile (separate groups)
        #pragma unroll
        for (int i = 0; i < 4; i++) {
            int id = i * 256 + tid;
            int r = id >> 4, c = (id & 15) << 2;
            cp_async16(k_u32 + (uint32_t)(r * FW + c) * 4,
                       qkv + kb + (long)r * C3 + 1024 + c);
        }
        CP_COMMIT;
        #pragma unroll
        for (int i = 0; i < 4; i++) {
            int id = i * 256 + tid;
            int r = id >> 4, c = (id & 15) << 2;
            cp_async16(v_u32 + (uint32_t)(r * FWV + c) * 4,
                       qkv + kb + (long)r * C3 + 2048 + c);
        }
        CP_COMMIT;

        cp_wait<1>();        // K done (V may be in flight)
        __syncthreads();

        // S = Q @ K^T  (rows m0..m0+15, cols 0..63)
        float Sf[8][4];
        #pragma unroll
        for (int nf = 0; nf < 8; nf++)
            #pragma unroll
            for (int e = 0; e < 4; e++) Sf[nf][e] = 0.f;

        #pragma unroll
        for (int k8 = 0; k8 < 64; k8 += 8) {
            uint32_t a0 = __float_as_uint(Qs[(m0 + g)     * FW + k8 + t]);
            uint32_t a1 = __float_as_uint(Qs[(m0 + g + 8) * FW + k8 + t]);
            uint32_t a2 = __float_as_uint(Qs[(m0 + g)     * FW + k8 + t + 4]);
            uint32_t a3 = __float_as_uint(Qs[(m0 + g + 8) * FW + k8 + t + 4]);
            #pragma unroll
            for (int nf = 0; nf < 8; nf++) {
                uint32_t b0 = __float_as_uint(Ks[(nf * 8 + g) * FW + k8 + t]);
                uint32_t b1 = __float_as_uint(Ks[(nf * 8 + g) * FW + k8 + t + 4]);
                mma_tf32(Sf[nf][0], Sf[nf][1], Sf[nf][2], Sf[nf][3],
                         a0, a1, a2, a3, b0, b1);
            }
        }

        // Online softmax (exp2 domain); write P to smem
        #pragma unroll
        for (int r = 0; r < 2; r++) {
            const int e = r * 2;
            float mx = -1e30f;
            #pragma unroll
            for (int nf = 0; nf < 8; nf++)
                mx = fmaxf(mx, fmaxf(Sf[nf][e], Sf[nf][e + 1]));
            mx = fmaxf(mx, __shfl_xor_sync(0xffffffffu, mx, 1));
            mx = fmaxf(mx, __shfl_xor_sync(0xffffffffu, mx, 2));
            const float nm = fmaxf(m_[r], mx);
            const float corr = exp2f(m_[r] - nm);
            float ps = 0.f;
            #pragma unroll
            for (int nf = 0; nf < 8; nf++) {
                Sf[nf][e]     = exp2f(Sf[nf][e] - nm);
                Sf[nf][e + 1] = exp2f(Sf[nf][e + 1] - nm);
                ps += Sf[nf][e] + Sf[nf][e + 1];
            }
            ps += __shfl_xor_sync(0xffffffffu, ps, 1);
            ps += __shfl_xor_sync(0xffffffffu, ps, 2);
            l_[r] = l_[r] * corr + ps;
            m_[r] = nm;
            #pragma unroll
            for (int nf = 0; nf < 8; nf++) {
                Of[nf][e] *= corr; Of[nf][e + 1] *= corr;
            }
            const int row = m0 + g + r * 8;
            #pragma unroll
            for (int nf = 0; nf < 8; nf++) {
                float2 p2 = make_float2(to_tf32(Sf[nf][e]), to_tf32(Sf[nf][e + 1]));
                *reinterpret_cast<float2*>(Ps + row * FW + nf * 8 + 2 * t) = p2;
            }
        }

        cp_wait<0>();        // V done
        __syncthreads();     // P + V visible to all

        // O += P @ V
        #pragma unroll
        for (int k8 = 0; k8 < 64; k8 += 8) {
            uint32_t a0 = __float_as_uint(Ps[(m0 + g)     * FW + k8 + t]);
            uint32_t a1 = __float_as_uint(Ps[(m0 + g + 8) * FW + k8 + t]);
            uint32_t a2 = __float_as_uint(Ps[(m0 + g)     * FW + k8 + t + 4]);
            uint32_t a3 = __float_as_uint(Ps[(m0 + g + 8) * FW + k8 + t + 4]);
            #pragma unroll
            for (int nf = 0; nf < 8; nf++) {
                uint32_t b0 = __float_as_uint(Vs[(k8 + t)     * FWV + nf * 8 + g]);
                uint32_t b1 = __float_as_uint(Vs[(k8 + t + 4) * FWV + nf * 8 + g]);
                mma_tf32(Of[nf][0], Of[nf][1], Of[nf][2], Of[nf][3],
                         a0, a1, a2, a3, b0, b1);
            }
        }
    }

    // Epilogue: normalize, round (feeds proj GEMM), store merged heads
    #pragma unroll
    for (int r = 0; r < 2; r++) {
        const float inv = 1.0f / l_[r];
        const long row = (long)b * SEQ + q0 + m0 + g + r * 8;
        const int e = r * 2;
        #pragma unroll
        for (int nf = 0; nf < 8; nf++) {
            float2 o = make_float2(to_tf32(Of[nf][e] * inv),
                                   to_tf32(Of[nf][e + 1] * inv));
            *reinterpret_cast<float2*>(out + row * DIM + h * HD + nf * 8 + 2 * t) = o;
        }
    }
}

// ---------------------------------------------------------------------------
// Elementwise tf32 rounding (weights, once per launch)
// ---------------------------------------------------------------------------
__global__ void __launch_bounds__(256) round4(
    const float* __restrict__ in, float* __restrict__ out, int n4)
{
    int i = blockIdx.x * 256 + threadIdx.x;
    if (i < n4) {
        float4 v = reinterpret_cast<const float4*>(in)[i];
        v.x = to_tf32(v.x); v.y = to_tf32(v.y);
        v.z = to_tf32(v.z); v.w = to_tf32(v.w);
        reinterpret_cast<float4*>(out)[i] = v;
    }
}

// ---------------------------------------------------------------------------
// LayerNorm (output rounded to tf32 — always feeds a GEMM A-operand)
// ---------------------------------------------------------------------------
__global__ void __launch_bounds__(256) ln_kernel(
    const float* __restrict__ x, const float* __restrict__ g,
    const float* __restrict__ b, float* __restrict__ out)
{
    const int row = blockIdx.x;
    const int tid = threadIdx.x;
    const float4* xr = reinterpret_cast<const float4*>(x + (long)row * DIM);
    float4 v = xr[tid];

    __shared__ float red1[8];
    __shared__ float red2[8];

    float s = v.x + v.y + v.z + v.w;
    #pragma unroll
    for (int off = 16; off; off >>= 1) s += __shfl_xor_sync(0xffffffffu, s, off);
    if ((tid & 31) == 0) red1[tid >> 5] = s;
    __syncthreads();
    float tot = 0.f;
    #pragma unroll
    for (int w = 0; w < 8; w++) tot += red1[w];
    const float mean = tot * (1.0f / DIM);

    float dx = v.x - mean, dy = v.y - mean, dz = v.z - mean, dw = v.w - mean;
    float q = dx * dx + dy * dy + dz * dz + dw * dw;
    #pragma unroll
    for (int off = 16; off; off >>= 1) q += __shfl_xor_sync(0xffffffffu, q, off);
    if ((tid & 31) == 0) red2[tid >> 5] = q;
    __syncthreads();
    float qtot = 0.f;
    #pragma unroll
    for (int w = 0; w < 8; w++) qtot += red2[w];
    const float rstd = rsqrtf(qtot * (1.0f / DIM) + 1e-5f);

    float4 gv = reinterpret_cast<const float4*>(g)[tid];
    float4 bv = reinterpret_cast<const float4*>(b)[tid];
    float4 o;
    o.x = to_tf32(dx * rstd * gv.x + bv.x);
    o.y = to_tf32(dy * rstd * gv.y + bv.y);
    o.z = to_tf32(dz * rstd * gv.z + bv.z);
    o.w = to_tf32(dw * rstd * gv.w + bv.w);
    reinterpret_cast<float4*>(out + (long)row * DIM)[tid] = o;
}

// ---------------------------------------------------------------------------
// Launch
// ---------------------------------------------------------------------------
extern "C" void kernel_launch(void* const* d_in, const int* in_sizes, int n_in,
                              void* d_out, int out_size)
{
    const float* x      = (const float*)d_in[0];
    const float* ln1_g  = (const float*)d_in[1];
    const float* ln1_b  = (const float*)d_in[2];
    const float* w_qkv  = (const float*)d_in[3];
    const float* w_proj = (const float*)d_in[4];
    const float* b_proj = (const float*)d_in[5];
    const float* ln2_g  = (const float*)d_in[6];
    const float* ln2_b  = (const float*)d_in[7];
    const float* w1     = (const float*)d_in[8];
    const float* b1     = (const float*)d_in[9];
    const float* w2     = (const float*)d_in[10];
    const float* b2     = (const float*)d_in[11];
    float* out = (float*)d_out;

    float *h1, *qkv, *attn, *x1, *h2, *hid, *wqkv_r, *wproj_r, *w1_r, *w2_r;
    cudaGetSymbolAddress((void**)&h1,      g_h1);
    cudaGetSymbolAddress((void**)&qkv,     g_qkv);
    cudaGetSymbolAddress((void**)&attn,    g_attn);
    cudaGetSymbolAddress((void**)&x1,      g_x1);
    cudaGetSymbolAddress((void**)&h2,      g_h2);
    cudaGetSymbolAddress((void**)&hid,     g_hid);
    cudaGetSymbolAddress((void**)&wqkv_r,  g_wqkv);
    cudaGetSymbolAddress((void**)&wproj_r, g_wproj);
    cudaGetSymbolAddress((void**)&w1_r,    g_w1);
    cudaGetSymbolAddress((void**)&w2_r,    g_w2);

    static bool attr_done = false;
    if (!attr_done) {
        cudaFuncSetAttribute(mma_gemm<0,1>, cudaFuncAttributeMaxDynamicSharedMemorySize, GEMM_SMEM);
        cudaFuncSetAttribute(mma_gemm<5,0>, cudaFuncAttributeMaxDynamicSharedMemorySize, GEMM_SMEM);
        cudaFuncSetAttribute(mma_gemm<3,1>, cudaFuncAttributeMaxDynamicSharedMemorySize, GEMM_SMEM);
        cudaFuncSetAttribute(flash_mma,     cudaFuncAttributeMaxDynamicSharedMemorySize, FLASH_SMEM);
        attr_done = true;
    }

    // Round weights to tf32 (rna) once per launch
    round4<<<(DIM * C3 / 4 + 255) / 256, 256>>>(w_qkv,  wqkv_r,  DIM * C3 / 4);
    round4<<<(DIM * DIM / 4 + 255) / 256, 256>>>(w_proj, wproj_r, DIM * DIM / 4);
    round4<<<(DIM * HIDDEN / 4 + 255) / 256, 256>>>(w1,  w1_r,    DIM * HIDDEN / 4);
    round4<<<(HIDDEN * DIM / 4 + 255) / 256, 256>>>(w2,  w2_r,    HIDDEN * DIM / 4);

    // 1) h1 = LN1(x)         (rounded)
    ln_kernel<<<TOK, 256>>>(x, ln1_g, ln1_b, h1);

    // 2) qkv = h1 @ w_qkv    (rounded output -> Q,K,V are tf32-clean)
    mma_gemm<0,1><<<dim3(C3 / 128, TOK / 128), 256, GEMM_SMEM>>>(
        h1, wqkv_r, nullptr, nullptr, qkv, TOK, C3, DIM);

    // 3) attention (tensor-core flash; output rounded)
    flash_mma<<<dim3(SEQ / 128, BATCH * HEADS), 256, FLASH_SMEM>>>(qkv, attn);

    // 4) x1 = x + attn @ w_proj + b_proj   (full fp32 residual)
    mma_gemm<5,0><<<dim3(DIM / 128, TOK / 128), 256, GEMM_SMEM>>>(
        attn, wproj_r, b_proj, x, x1, TOK, DIM, DIM);

    // 5) h2 = LN2(x1)        (rounded)
    ln_kernel<<<TOK, 256>>>(x1, ln2_g, ln2_b, h2);

    // 6) hid = gelu(h2 @ w1 + b1)   (rounded output)
    mma_gemm<3,1><<<dim3(HIDDEN / 128, TOK / 128), 256, GEMM_SMEM>>>(
        h2, w1_r, b1, nullptr, hid, TOK, HIDDEN, DIM);

    // 7) out = x1 + hid @ w2 + b2   (full fp32)
    mma_gemm<5,0><<<dim3(DIM / 128, TOK / 128), 256, GEMM_SMEM>>>(
        hid, w2_r, b2, x1, out, TOK, DIM, HIDDEN);
}

// round 5
// speedup vs baseline: 4.1011x; 1.0645x over previous
#include <cuda_runtime.h>
#include <cstdint>
#include <math.h>

// ---------------------------------------------------------------------------
// Problem dims
// ---------------------------------------------------------------------------
#define BATCH   2
#define SEQ     2048
#define TOK     (BATCH * SEQ)      // 4096
#define DIM     1024
#define HEADS   16
#define HD      64
#define HIDDEN  (4 * DIM)          // 4096
#define C3      (3 * DIM)          // 3072

// ---------------------------------------------------------------------------
// Scratch (device globals; no allocations allowed)
// ---------------------------------------------------------------------------
__device__ float g_h1  [TOK * DIM];
__device__ float g_qkv [TOK * C3];
__device__ float g_attn[TOK * DIM];
__device__ float g_x1  [TOK * DIM];
__device__ float g_h2  [TOK * DIM];
__device__ float g_hid [TOK * HIDDEN];
__device__ float g_wqkv [DIM * C3];
__device__ float g_wproj[DIM * DIM];
__device__ float g_w1   [DIM * HIDDEN];
__device__ float g_w2   [HIDDEN * DIM];

// ---------------------------------------------------------------------------
// Helpers
// ---------------------------------------------------------------------------
__device__ __forceinline__ uint32_t smem_u32(const void* p) {
    uint32_t a;
    asm("{ .reg .u64 t; cvta.to.shared.u64 t, %1; cvt.u32.u64 %0, t; }" : "=r"(a) : "l"(p));
    return a;
}
__device__ __forceinline__ float to_tf32(float x) {
    float y; asm("cvt.rna.tf32.f32 %0, %1;" : "=f"(y) : "f"(x)); return y;
}
__device__ __forceinline__ float gelu_erf(float v) {
    return 0.5f * v * (1.0f + erff(v * 0.70710678118654752440f));
}
__device__ __forceinline__ void mma_tf32(
    float& d0, float& d1, float& d2, float& d3,
    uint32_t a0, uint32_t a1, uint32_t a2, uint32_t a3,
    uint32_t b0, uint32_t b1)
{
    asm volatile(
        "mma.sync.aligned.m16n8k8.row.col.f32.tf32.tf32.f32 "
        "{%0,%1,%2,%3}, {%4,%5,%6,%7}, {%8,%9}, {%0,%1,%2,%3};"
        : "+f"(d0), "+f"(d1), "+f"(d2), "+f"(d3)
        : "r"(a0), "r"(a1), "r"(a2), "r"(a3), "r"(b0), "r"(b1));
}
__device__ __forceinline__ void cp_async16(uint32_t dst, const void* src) {
    asm volatile("cp.async.cg.shared.global [%0], [%1], 16;" :: "r"(dst), "l"(src));
}
#define CP_COMMIT asm volatile("cp.async.commit_group;")
template <int N>
__device__ __forceinline__ void cp_wait() {
    asm volatile("cp.async.wait_group %0;" :: "n"(N));
}

// ---------------------------------------------------------------------------
// tf32 GEMM: C[M,N] = A[M,K] @ B[K,N], pre-rounded inputs.
// 128x128 tile, 4 warps (2x2), warp tile 64x64, BK=32, 3-stage cp.async.
// EPI: 1=bias, 2=gelu, 4=residual.  RND: round output to tf32.
// ---------------------------------------------------------------------------
#define AS_ST 36
#define BS_ST 136
#define AS_FL (128 * AS_ST)
#define BS_FL (32 * BS_ST)
#define GEMM_SMEM ((3 * AS_FL + 3 * BS_FL) * 4)  // 107520 bytes

template <int EPI, int RND>
__global__ void __launch_bounds__(128, 2) mma_gemm(
    const float* __restrict__ A, const float* __restrict__ B,
    const float* __restrict__ bias, const float* __restrict__ R,
    float* __restrict__ C, int M, int N, int K)
{
    extern __shared__ float sm[];
    float* Asm = sm;
    float* Bsm = sm + 3 * AS_FL;
    const uint32_t a_u32 = smem_u32(Asm);
    const uint32_t b_u32 = smem_u32(Bsm);

    const int tid = threadIdx.x;
    const int lane = tid & 31, warp = tid >> 5;
    const int wy = warp >> 1, wx = warp & 1;
    const int g = lane >> 2, t = lane & 3;
    const int bm = blockIdx.y * 128, bn = blockIdx.x * 128;

    auto issue = [&](int s, int k0) {
        #pragma unroll
        for (int w = 0; w < 8; w++) {
            int id = w * 128 + tid;
            int r = id >> 3, c = (id & 7) << 2;
            cp_async16(a_u32 + (uint32_t)(s * AS_FL + r * AS_ST + c) * 4,
                       A + (long)(bm + r) * K + k0 + c);
        }
        #pragma unroll
        for (int w = 0; w < 8; w++) {
            int id = w * 128 + tid;
            int r = id >> 5, c = (id & 31) << 2;
            cp_async16(b_u32 + (uint32_t)(s * BS_FL + r * BS_ST + c) * 4,
                       B + (long)(k0 + r) * N + bn + c);
        }
        CP_COMMIT;
    };

    float acc[4][8][4];
    #pragma unroll
    for (int i = 0; i < 4; i++)
        #pragma unroll
        for (int j = 0; j < 8; j++)
            #pragma unroll
            for (int e = 0; e < 4; e++) acc[i][j][e] = 0.f;

    const int NK = K >> 5;
    issue(0, 0);
    issue(1, 32);

    for (int it = 0; it < NK; ++it) {
        if (it == NK - 1) { cp_wait<0>(); } else { cp_wait<1>(); }
        __syncthreads();
        if (it + 2 < NK) issue((it + 2) % 3, (it + 2) << 5);

        const float* as = Asm + (it % 3) * AS_FL;
        const float* bs = Bsm + (it % 3) * BS_FL;
        #pragma unroll
        for (int k8 = 0; k8 < 32; k8 += 8) {
            uint32_t af[4][4], bf[8][2];
            #pragma unroll
            for (int mf = 0; mf < 4; mf++) {
                const int m0 = wy * 64 + mf * 16;
                af[mf][0] = __float_as_uint(as[(m0 + g)     * AS_ST + k8 + t]);
                af[mf][1] = __float_as_uint(as[(m0 + g + 8) * AS_ST + k8 + t]);
                af[mf][2] = __float_as_uint(as[(m0 + g)     * AS_ST + k8 + t + 4]);
                af[mf][3] = __float_as_uint(as[(m0 + g + 8) * AS_ST + k8 + t + 4]);
            }
            #pragma unroll
            for (int nf = 0; nf < 8; nf++) {
                const int n0 = wx * 64 + nf * 8;
                bf[nf][0] = __float_as_uint(bs[(k8 + t)     * BS_ST + n0 + g]);
                bf[nf][1] = __float_as_uint(bs[(k8 + t + 4) * BS_ST + n0 + g]);
            }
            #pragma unroll
            for (int mf = 0; mf < 4; mf++)
                #pragma unroll
                for (int nf = 0; nf < 8; nf++)
                    mma_tf32(acc[mf][nf][0], acc[mf][nf][1],
                             acc[mf][nf][2], acc[mf][nf][3],
                             af[mf][0], af[mf][1], af[mf][2], af[mf][3],
                             bf[nf][0], bf[nf][1]);
        }
    }

    // Epilogue
    #pragma unroll
    for (int mf = 0; mf < 4; mf++) {
        const long row = bm + wy * 64 + mf * 16 + g;
        #pragma unroll
        for (int nf = 0; nf < 8; nf++) {
            const long col = bn + wx * 64 + nf * 8 + t * 2;
            float2 v0 = make_float2(acc[mf][nf][0], acc[mf][nf][1]);
            float2 v1 = make_float2(acc[mf][nf][2], acc[mf][nf][3]);
            if (EPI & 1) {
                const float2 bv = *reinterpret_cast<const float2*>(bias + col);
                v0.x += bv.x; v0.y += bv.y;
                v1.x += bv.x; v1.y += bv.y;
            }
            if (EPI & 2) {
                v0.x = gelu_erf(v0.x); v0.y = gelu_erf(v0.y);
                v1.x = gelu_erf(v1.x); v1.y = gelu_erf(v1.y);
            }
            if (EPI & 4) {
                const float2 r0 = *reinterpret_cast<const float2*>(R + row * N + col);
                const float2 r1 = *reinterpret_cast<const float2*>(R + (row + 8) * N + col);
                v0.x += r0.x; v0.y += r0.y;
                v1.x += r1.x; v1.y += r1.y;
            }
            if (RND) {
                v0.x = to_tf32(v0.x); v0.y = to_tf32(v0.y);
                v1.x = to_tf32(v1.x); v1.y = to_tf32(v1.y);
            }
            *reinterpret_cast<float2*>(C + row * N + col) = v0;
            *reinterpret_cast<float2*>(C + (row + 8) * N + col) = v1;
        }
    }
}

// ---------------------------------------------------------------------------
// Flash attention, tf32 mma. 128 q-rows/CTA, 8 warps x 16 rows.
// Q fragments in registers. K/V double-buffered, prefetched 1 tile ahead.
// exp2-domain softmax (Q pre-scaled by 0.125*log2 e).
// ---------------------------------------------------------------------------
#define FW  68
#define FWV 72
#define FP_OFF 0
#define FK_OFF (128 * FW)                  // 8704
#define FV_OFF (FK_OFF + 2 * 64 * FW)      // 17408
#define FLASH_SMEM ((FV_OFF + 2 * 64 * FWV) * 4)   // 106496 bytes

__global__ void __launch_bounds__(256) flash_mma(
    const float* __restrict__ qkv, float* __restrict__ out)
{
    extern __shared__ float sm[];
    float* Ps = sm + FP_OFF;
    const uint32_t k_u32 = smem_u32(sm + FK_OFF);
    const uint32_t v_u32 = smem_u32(sm + FV_OFF);

    const int tid = threadIdx.x;
    const int lane = tid & 31, warp = tid >> 5;
    const int g = lane >> 2, t = lane & 3;
    const int b = blockIdx.y >> 4, h = blockIdx.y & 15;
    const int q0 = blockIdx.x * 128;
    const int m0 = warp * 16;
    const long base = (long)b * SEQ * C3 + h * HD;

    // Q fragments -> registers (scaled, tf32-rounded). 32 regs.
    const float qscale = 0.125f * 1.4426950408889634f;
    uint32_t qf[8][4];
    {
        const float* q_lo = qkv + base + (long)(q0 + m0 + g) * C3;
        const float* q_hi = qkv + base + (long)(q0 + m0 + g + 8) * C3;
        #pragma unroll
        for (int s = 0; s < 8; s++) {
            qf[s][0] = __float_as_uint(to_tf32(q_lo[s * 8 + t]     * qscale));
            qf[s][1] = __float_as_uint(to_tf32(q_hi[s * 8 + t]     * qscale));
            qf[s][2] = __float_as_uint(to_tf32(q_lo[s * 8 + t + 4] * qscale));
            qf[s][3] = __float_as_uint(to_tf32(q_hi[s * 8 + t + 4] * qscale));
        }
    }

    // issue K+V tile kt into buffer bf (one commit group)
    auto issue_kv = [&](int kt, int bf) {
        const long kb = base + (long)(kt * 64) * C3;
        #pragma unroll
        for (int i = 0; i < 4; i++) {
            int id = i * 256 + tid;
            int r = id >> 4, c = (id & 15) << 2;
            cp_async16(k_u32 + (uint32_t)(bf * 64 * FW + r * FW + c) * 4,
                       qkv + kb + (long)r * C3 + 1024 + c);
        }
        #pragma unroll
        for (int i = 0; i < 4; i++) {
            int id = i * 256 + tid;
            int r = id >> 4, c = (id & 15) << 2;
            cp_async16(v_u32 + (uint32_t)(bf * 64 * FWV + r * FWV + c) * 4,
                       qkv + kb + (long)r * C3 + 2048 + c);
        }
        CP_COMMIT;
    };

    float Of[8][4];
    #pragma unroll
    for (int nf = 0; nf < 8; nf++)
        #pragma unroll
        for (int e = 0; e < 4; e++) Of[nf][e] = 0.f;
    float m_[2] = {-1e30f, -1e30f};
    float l_[2] = {0.f, 0.f};

    issue_kv(0, 0);

    const int NT = SEQ / 64;
    for (int kt = 0; kt < NT; kt++) {
        const int buf = kt & 1;
        __syncthreads();                       // all warps done with buf^1
        if (kt + 1 < NT) { issue_kv(kt + 1, buf ^ 1); cp_wait<1>(); }
        else             { cp_wait<0>(); }
        __syncthreads();                       // tile kt visible

        const float* Ks = sm + FK_OFF + buf * 64 * FW;
        const float* Vs = sm + FV_OFF + buf * 64 * FWV;

        // S = Q @ K^T
        float Sf[8][4];
        #pragma unroll
        for (int nf = 0; nf < 8; nf++)
            #pragma unroll
            for (int e = 0; e < 4; e++) Sf[nf][e] = 0.f;

        #pragma unroll
        for (int s = 0; s < 8; s++) {
            const int k8 = s * 8;
            #pragma unroll
            for (int nf = 0; nf < 8; nf++) {
                uint32_t b0 = __float_as_uint(Ks[(nf * 8 + g) * FW + k8 + t]);
                uint32_t b1 = __float_as_uint(Ks[(nf * 8 + g) * FW + k8 + t + 4]);
                mma_tf32(Sf[nf][0], Sf[nf][1], Sf[nf][2], Sf[nf][3],
                         qf[s][0], qf[s][1], qf[s][2], qf[s][3], b0, b1);
            }
        }

        // Online softmax; P -> smem (warp-private rows)
        #pragma unroll
        for (int r = 0; r < 2; r++) {
            const int e = r * 2;
            float mx = -1e30f;
            #pragma unroll
            for (int nf = 0; nf < 8; nf++)
                mx = fmaxf(mx, fmaxf(Sf[nf][e], Sf[nf][e + 1]));
            mx = fmaxf(mx, __shfl_xor_sync(0xffffffffu, mx, 1));
            mx = fmaxf(mx, __shfl_xor_sync(0xffffffffu, mx, 2));
            const float nm = fmaxf(m_[r], mx);
            const float corr = exp2f(m_[r] - nm);
            float ps = 0.f;
            #pragma unroll
            for (int nf = 0; nf < 8; nf++) {
                Sf[nf][e]     = exp2f(Sf[nf][e] - nm);
                Sf[nf][e + 1] = exp2f(Sf[nf][e + 1] - nm);
                ps += Sf[nf][e] + Sf[nf][e + 1];
            }
            ps += __shfl_xor_sync(0xffffffffu, ps, 1);
            ps += __shfl_xor_sync(0xffffffffu, ps, 2);
            l_[r] = l_[r] * corr + ps;
            m_[r] = nm;
            #pragma unroll
            for (int nf = 0; nf < 8; nf++) {
                Of[nf][e] *= corr; Of[nf][e + 1] *= corr;
            }
            const int row = m0 + g + r * 8;
            #pragma unroll
            for (int nf = 0; nf < 8; nf++) {
                float2 p2 = make_float2(to_tf32(Sf[nf][e]), to_tf32(Sf[nf][e + 1]));
                *reinterpret_cast<float2*>(Ps + row * FW + nf * 8 + 2 * t) = p2;
            }
        }
        __syncwarp();      // P write->read is within-warp only

        // O += P @ V
        #pragma unroll
        for (int s = 0; s < 8; s++) {
            const int k8 = s * 8;
            uint32_t a0 = __float_as_uint(Ps[(m0 + g)     * FW + k8 + t]);
            uint32_t a1 = __float_as_uint(Ps[(m0 + g + 8) * FW + k8 + t]);
            uint32_t a2 = __float_as_uint(Ps[(m0 + g)     * FW + k8 + t + 4]);
            uint32_t a3 = __float_as_uint(Ps[(m0 + g + 8) * FW + k8 + t + 4]);
            #pragma unroll
            for (int nf = 0; nf < 8; nf++) {
                uint32_t b0 = __float_as_uint(Vs[(k8 + t)     * FWV + nf * 8 + g]);
                uint32_t b1 = __float_as_uint(Vs[(k8 + t + 4) * FWV + nf * 8 + g]);
                mma_tf32(Of[nf][0], Of[nf][1], Of[nf][2], Of[nf][3],
                         a0, a1, a2, a3, b0, b1);
            }
        }
    }

    // Normalize, round, store merged heads
    #pragma unroll
    for (int r = 0; r < 2; r++) {
        const float inv = 1.0f / l_[r];
        const long row = (long)b * SEQ + q0 + m0 + g + r * 8;
        const int e = r * 2;
        #pragma unroll
        for (int nf = 0; nf < 8; nf++) {
            float2 o = make_float2(to_tf32(Of[nf][e] * inv),
                                   to_tf32(Of[nf][e + 1] * inv));
            *reinterpret_cast<float2*>(out + row * DIM + h * HD + nf * 8 + 2 * t) = o;
        }
    }
}

// ---------------------------------------------------------------------------
// Elementwise tf32 rounding (weights)
// ---------------------------------------------------------------------------
__global__ void __launch_bounds__(256) round4(
    const float* __restrict__ in, float* __restrict__ out, int n4)
{
    int i = blockIdx.x * 256 + threadIdx.x;
    if (i < n4) {
        float4 v = reinterpret_cast<const float4*>(in)[i];
        v.x = to_tf32(v.x); v.y = to_tf32(v.y);
        v.z = to_tf32(v.z); v.w = to_tf32(v.w);
        reinterpret_cast<float4*>(out)[i] = v;
    }
}

// ---------------------------------------------------------------------------
// LayerNorm (tf32-rounded output)
// ---------------------------------------------------------------------------
__global__ void __launch_bounds__(256) ln_kernel(
    const float* __restrict__ x, const float* __restrict__ g,
    const float* __restrict__ b, float* __restrict__ out)
{
    const int row = blockIdx.x;
    const int tid = threadIdx.x;
    const float4* xr = reinterpret_cast<const float4*>(x + (long)row * DIM);
    float4 v = xr[tid];

    __shared__ float red1[8];
    __shared__ float red2[8];

    float s = v.x + v.y + v.z + v.w;
    #pragma unroll
    for (int off = 16; off; off >>= 1) s += __shfl_xor_sync(0xffffffffu, s, off);
    if ((tid & 31) == 0) red1[tid >> 5] = s;
    __syncthreads();
    float tot = 0.f;
    #pragma unroll
    for (int w = 0; w < 8; w++) tot += red1[w];
    const float mean = tot * (1.0f / DIM);

    float dx = v.x - mean, dy = v.y - mean, dz = v.z - mean, dw = v.w - mean;
    float q = dx * dx + dy * dy + dz * dz + dw * dw;
    #pragma unroll
    for (int off = 16; off; off >>= 1) q += __shfl_xor_sync(0xffffffffu, q, off);
    if ((tid & 31) == 0) red2[tid >> 5] = q;
    __syncthreads();
    float qtot = 0.f;
    #pragma unroll
    for (int w = 0; w < 8; w++) qtot += red2[w];
    const float rstd = rsqrtf(qtot * (1.0f / DIM) + 1e-5f);

    float4 gv = reinterpret_cast<const float4*>(g)[tid];
    float4 bv = reinterpret_cast<const float4*>(b)[tid];
    float4 o;
    o.x = to_tf32(dx * rstd * gv.x + bv.x);
    o.y = to_tf32(dy * rstd * gv.y + bv.y);
    o.z = to_tf32(dz * rstd * gv.z + bv.z);
    o.w = to_tf32(dw * rstd * gv.w + bv.w);
    reinterpret_cast<float4*>(out + (long)row * DIM)[tid] = o;
}

// ---------------------------------------------------------------------------
// Launch
// ---------------------------------------------------------------------------
extern "C" void kernel_launch(void* const* d_in, const int* in_sizes, int n_in,
                              void* d_out, int out_size)
{
    const float* x      = (const float*)d_in[0];
    const float* ln1_g  = (const float*)d_in[1];
    const float* ln1_b  = (const float*)d_in[2];
    const float* w_qkv  = (const float*)d_in[3];
    const float* w_proj = (const float*)d_in[4];
    const float* b_proj = (const float*)d_in[5];
    const float* ln2_g  = (const float*)d_in[6];
    const float* ln2_b  = (const float*)d_in[7];
    const float* w1     = (const float*)d_in[8];
    const float* b1     = (const float*)d_in[9];
    const float* w2     = (const float*)d_in[10];
    const float* b2     = (const float*)d_in[11];
    float* out = (float*)d_out;

    float *h1, *qkv, *attn, *x1, *h2, *hid, *wqkv_r, *wproj_r, *w1_r, *w2_r;
    cudaGetSymbolAddress((void**)&h1,      g_h1);
    cudaGetSymbolAddress((void**)&qkv,     g_qkv);
    cudaGetSymbolAddress((void**)&attn,    g_attn);
    cudaGetSymbolAddress((void**)&x1,      g_x1);
    cudaGetSymbolAddress((void**)&h2,      g_h2);
    cudaGetSymbolAddress((void**)&hid,     g_hid);
    cudaGetSymbolAddress((void**)&wqkv_r,  g_wqkv);
    cudaGetSymbolAddress((void**)&wproj_r, g_wproj);
    cudaGetSymbolAddress((void**)&w1_r,    g_w1);
    cudaGetSymbolAddress((void**)&w2_r,    g_w2);

    cudaFuncSetAttribute(mma_gemm<0,1>, cudaFuncAttributeMaxDynamicSharedMemorySize, GEMM_SMEM);
    cudaFuncSetAttribute(mma_gemm<5,0>, cudaFuncAttributeMaxDynamicSharedMemorySize, GEMM_SMEM);
    cudaFuncSetAttribute(mma_gemm<3,1>, cudaFuncAttributeMaxDynamicSharedMemorySize, GEMM_SMEM);
    cudaFuncSetAttribute(flash_mma,     cudaFuncAttributeMaxDynamicSharedMemorySize, FLASH_SMEM);

    // tf32 weight copies
    round4<<<(DIM * C3 / 4 + 255) / 256, 256>>>(w_qkv,  wqkv_r,  DIM * C3 / 4);
    round4<<<(DIM * DIM / 4 + 255) / 256, 256>>>(w_proj, wproj_r, DIM * DIM / 4);
    round4<<<(DIM * HIDDEN / 4 + 255) / 256, 256>>>(w1,  w1_r,    DIM * HIDDEN / 4);
    round4<<<(HIDDEN * DIM / 4 + 255) / 256, 256>>>(w2,  w2_r,    HIDDEN * DIM / 4);

    // 1) h1 = LN1(x)
    ln_kernel<<<TOK, 256>>>(x, ln1_g, ln1_b, h1);

    // 2) qkv = h1 @ w_qkv
    mma_gemm<0,1><<<dim3(C3 / 128, TOK / 128), 128, GEMM_SMEM>>>(
        h1, wqkv_r, nullptr, nullptr, qkv, TOK, C3, DIM);

    // 3) attention
    flash_mma<<<dim3(SEQ / 128, BATCH * HEADS), 256, FLASH_SMEM>>>(qkv, attn);

    // 4) x1 = x + attn @ w_proj + b_proj
    mma_gemm<5,0><<<dim3(DIM / 128, TOK / 128), 128, GEMM_SMEM>>>(
        attn, wproj_r, b_proj, x, x1, TOK, DIM, DIM);

    // 5) h2 = LN2(x1)
    ln_kernel<<<TOK, 256>>>(x1, ln2_g, ln2_b, h2);

    // 6) hid = gelu(h2 @ w1 + b1)
    mma_gemm<3,1><<<dim3(HIDDEN / 128, TOK / 128), 128, GEMM_SMEM>>>(
        h2, w1_r, b1, nullptr, hid, TOK, HIDDEN, DIM);

    // 7) out = x1 + hid @ w2 + b2
    mma_gemm<5,0><<<dim3(DIM / 128, TOK / 128), 128, GEMM_SMEM>>>(
        hid, w2_r, b2, x1, out, TOK, DIM, HIDDEN);
}

// round 6
// speedup vs baseline: 4.1086x; 1.0018x over previous
#include <cuda_runtime.h>
#include <cstdint>
#include <math.h>

// ---------------------------------------------------------------------------
// Problem dims
// ---------------------------------------------------------------------------
#define BATCH   2
#define SEQ     2048
#define TOK     (BATCH * SEQ)      // 4096
#define DIM     1024
#define HEADS   16
#define HD      64
#define HIDDEN  (4 * DIM)          // 4096
#define C3      (3 * DIM)          // 3072

// ---------------------------------------------------------------------------
// Scratch (device globals; no allocations allowed)
// ---------------------------------------------------------------------------
__device__ float g_h1  [TOK * DIM];
__device__ float g_qkv [TOK * C3];
__device__ float g_attn[TOK * DIM];
__device__ float g_x1  [TOK * DIM];
__device__ float g_h2  [TOK * DIM];
__device__ float g_hid [TOK * HIDDEN];
__device__ float g_wqkv [DIM * C3];
__device__ float g_wproj[DIM * DIM];
__device__ float g_w1   [DIM * HIDDEN];
__device__ float g_w2   [HIDDEN * DIM];

// ---------------------------------------------------------------------------
// Helpers
// ---------------------------------------------------------------------------
__device__ __forceinline__ uint32_t smem_u32(const void* p) {
    uint32_t a;
    asm("{ .reg .u64 t; cvta.to.shared.u64 t, %1; cvt.u32.u64 %0, t; }" : "=r"(a) : "l"(p));
    return a;
}
__device__ __forceinline__ float to_tf32(float x) {
    float y; asm("cvt.rna.tf32.f32 %0, %1;" : "=f"(y) : "f"(x)); return y;
}
__device__ __forceinline__ float gelu_erf(float v) {
    return 0.5f * v * (1.0f + erff(v * 0.70710678118654752440f));
}
__device__ __forceinline__ void mma_tf32(
    float& d0, float& d1, float& d2, float& d3,
    uint32_t a0, uint32_t a1, uint32_t a2, uint32_t a3,
    uint32_t b0, uint32_t b1)
{
    asm volatile(
        "mma.sync.aligned.m16n8k8.row.col.f32.tf32.tf32.f32 "
        "{%0,%1,%2,%3}, {%4,%5,%6,%7}, {%8,%9}, {%0,%1,%2,%3};"
        : "+f"(d0), "+f"(d1), "+f"(d2), "+f"(d3)
        : "r"(a0), "r"(a1), "r"(a2), "r"(a3), "r"(b0), "r"(b1));
}
__device__ __forceinline__ void cp_async16(uint32_t dst, const void* src) {
    asm volatile("cp.async.cg.shared.global [%0], [%1], 16;" :: "r"(dst), "l"(src));
}
#define CP_COMMIT asm volatile("cp.async.commit_group;")
template <int N>
__device__ __forceinline__ void cp_wait() {
    asm volatile("cp.async.wait_group %0;" :: "n"(N));
}

// ---------------------------------------------------------------------------
// tf32 GEMM: C[M,N] = A[M,K] @ B[K,N], pre-rounded inputs.
// 128x128 CTA tile, 8 warps (4m x 2n), warp tile 32x64, BK=32, 3-stage
// cp.async, 2 CTAs/SM (16 warps/SM).
// EPI: 1=bias, 2=gelu, 4=residual.  RND: round output to tf32.
// ---------------------------------------------------------------------------
#define AS_ST 36
#define BS_ST 136
#define AS_FL (128 * AS_ST)
#define BS_FL (32 * BS_ST)
#define GEMM_SMEM ((3 * AS_FL + 3 * BS_FL) * 4)  // 107520 bytes

template <int EPI, int RND>
__global__ void __launch_bounds__(256, 2) mma_gemm(
    const float* __restrict__ A, const float* __restrict__ B,
    const float* __restrict__ bias, const float* __restrict__ R,
    float* __restrict__ C, int M, int N, int K)
{
    extern __shared__ float sm[];
    float* Asm = sm;
    float* Bsm = sm + 3 * AS_FL;
    const uint32_t a_u32 = smem_u32(Asm);
    const uint32_t b_u32 = smem_u32(Bsm);

    const int tid = threadIdx.x;
    const int lane = tid & 31, warp = tid >> 5;
    const int wy = warp >> 1, wx = warp & 1;     // 4 x 2 warp grid
    const int g = lane >> 2, t = lane & 3;
    const int bm = blockIdx.y * 128, bn = blockIdx.x * 128;

    auto issue = [&](int s, int k0) {
        #pragma unroll
        for (int w = 0; w < 4; w++) {
            int id = w * 256 + tid;
            int r = id >> 3, c = (id & 7) << 2;
            cp_async16(a_u32 + (uint32_t)(s * AS_FL + r * AS_ST + c) * 4,
                       A + (long)(bm + r) * K + k0 + c);
        }
        #pragma unroll
        for (int w = 0; w < 4; w++) {
            int id = w * 256 + tid;
            int r = id >> 5, c = (id & 31) << 2;
            cp_async16(b_u32 + (uint32_t)(s * BS_FL + r * BS_ST + c) * 4,
                       B + (long)(k0 + r) * N + bn + c);
        }
        CP_COMMIT;
    };

    float acc[2][8][4];
    #pragma unroll
    for (int i = 0; i < 2; i++)
        #pragma unroll
        for (int j = 0; j < 8; j++)
            #pragma unroll
            for (int e = 0; e < 4; e++) acc[i][j][e] = 0.f;

    const int NK = K >> 5;
    issue(0, 0);
    issue(1, 32);

    for (int it = 0; it < NK; ++it) {
        if (it == NK - 1) { cp_wait<0>(); } else { cp_wait<1>(); }
        __syncthreads();
        if (it + 2 < NK) issue((it + 2) % 3, (it + 2) << 5);

        const float* as = Asm + (it % 3) * AS_FL;
        const float* bs = Bsm + (it % 3) * BS_FL;
        #pragma unroll
        for (int k8 = 0; k8 < 32; k8 += 8) {
            uint32_t af[2][4], bf[8][2];
            #pragma unroll
            for (int mf = 0; mf < 2; mf++) {
                const int m0 = wy * 32 + mf * 16;
                af[mf][0] = __float_as_uint(as[(m0 + g)     * AS_ST + k8 + t]);
                af[mf][1] = __float_as_uint(as[(m0 + g + 8) * AS_ST + k8 + t]);
                af[mf][2] = __float_as_uint(as[(m0 + g)     * AS_ST + k8 + t + 4]);
                af[mf][3] = __float_as_uint(as[(m0 + g + 8) * AS_ST + k8 + t + 4]);
            }
            #pragma unroll
            for (int nf = 0; nf < 8; nf++) {
                const int n0 = wx * 64 + nf * 8;
                bf[nf][0] = __float_as_uint(bs[(k8 + t)     * BS_ST + n0 + g]);
                bf[nf][1] = __float_as_uint(bs[(k8 + t + 4) * BS_ST + n0 + g]);
            }
            #pragma unroll
            for (int mf = 0; mf < 2; mf++)
                #pragma unroll
                for (int nf = 0; nf < 8; nf++)
                    mma_tf32(acc[mf][nf][0], acc[mf][nf][1],
                             acc[mf][nf][2], acc[mf][nf][3],
                             af[mf][0], af[mf][1], af[mf][2], af[mf][3],
                             bf[nf][0], bf[nf][1]);
        }
    }

    // Epilogue
    #pragma unroll
    for (int mf = 0; mf < 2; mf++) {
        const long row = bm + wy * 32 + mf * 16 + g;
        #pragma unroll
        for (int nf = 0; nf < 8; nf++) {
            const long col = bn + wx * 64 + nf * 8 + t * 2;
            float2 v0 = make_float2(acc[mf][nf][0], acc[mf][nf][1]);
            float2 v1 = make_float2(acc[mf][nf][2], acc[mf][nf][3]);
            if (EPI & 1) {
                const float2 bv = *reinterpret_cast<const float2*>(bias + col);
                v0.x += bv.x; v0.y += bv.y;
                v1.x += bv.x; v1.y += bv.y;
            }
            if (EPI & 2) {
                v0.x = gelu_erf(v0.x); v0.y = gelu_erf(v0.y);
                v1.x = gelu_erf(v1.x); v1.y = gelu_erf(v1.y);
            }
            if (EPI & 4) {
                const float2 r0 = *reinterpret_cast<const float2*>(R + row * N + col);
                const float2 r1 = *reinterpret_cast<const float2*>(R + (row + 8) * N + col);
                v0.x += r0.x; v0.y += r0.y;
                v1.x += r1.x; v1.y += r1.y;
            }
            if (RND) {
                v0.x = to_tf32(v0.x); v0.y = to_tf32(v0.y);
                v1.x = to_tf32(v1.x); v1.y = to_tf32(v1.y);
            }
            *reinterpret_cast<float2*>(C + row * N + col) = v0;
            *reinterpret_cast<float2*>(C + (row + 8) * N + col) = v1;
        }
    }
}

// ---------------------------------------------------------------------------
// Flash attention, tf32 mma. 128 q-rows/CTA, 8 warps x 16 rows.
// Q in registers. K/V double-buffered, prefetched one tile ahead.
// exp2-domain softmax. 2 CTAs/SM.
// ---------------------------------------------------------------------------
#define FW  68
#define FWV 72
#define FP_OFF 0
#define FK_OFF (128 * FW)                  // 8704
#define FV_OFF (FK_OFF + 2 * 64 * FW)      // 17408
#define FLASH_SMEM ((FV_OFF + 2 * 64 * FWV) * 4)   // 106496 bytes

__global__ void __launch_bounds__(256, 2) flash_mma(
    const float* __restrict__ qkv, float* __restrict__ out)
{
    extern __shared__ float sm[];
    float* Ps = sm + FP_OFF;
    const uint32_t k_u32 = smem_u32(sm + FK_OFF);
    const uint32_t v_u32 = smem_u32(sm + FV_OFF);

    const int tid = threadIdx.x;
    const int lane = tid & 31, warp = tid >> 5;
    const int g = lane >> 2, t = lane & 3;
    const int b = blockIdx.y >> 4, h = blockIdx.y & 15;
    const int q0 = blockIdx.x * 128;
    const int m0 = warp * 16;
    const long base = (long)b * SEQ * C3 + h * HD;

    // Q fragments -> registers (scaled, tf32-rounded). 32 regs.
    const float qscale = 0.125f * 1.4426950408889634f;
    uint32_t qf[8][4];
    {
        const float* q_lo = qkv + base + (long)(q0 + m0 + g) * C3;
        const float* q_hi = qkv + base + (long)(q0 + m0 + g + 8) * C3;
        #pragma unroll
        for (int s = 0; s < 8; s++) {
            qf[s][0] = __float_as_uint(to_tf32(q_lo[s * 8 + t]     * qscale));
            qf[s][1] = __float_as_uint(to_tf32(q_hi[s * 8 + t]     * qscale));
            qf[s][2] = __float_as_uint(to_tf32(q_lo[s * 8 + t + 4] * qscale));
            qf[s][3] = __float_as_uint(to_tf32(q_hi[s * 8 + t + 4] * qscale));
        }
    }

    auto issue_kv = [&](int kt, int bf) {
        const long kb = base + (long)(kt * 64) * C3;
        #pragma unroll
        for (int i = 0; i < 4; i++) {
            int id = i * 256 + tid;
            int r = id >> 4, c = (id & 15) << 2;
            cp_async16(k_u32 + (uint32_t)(bf * 64 * FW + r * FW + c) * 4,
                       qkv + kb + (long)r * C3 + 1024 + c);
        }
        #pragma unroll
        for (int i = 0; i < 4; i++) {
            int id = i * 256 + tid;
            int r = id >> 4, c = (id & 15) << 2;
            cp_async16(v_u32 + (uint32_t)(bf * 64 * FWV + r * FWV + c) * 4,
                       qkv + kb + (long)r * C3 + 2048 + c);
        }
        CP_COMMIT;
    };

    float Of[8][4];
    #pragma unroll
    for (int nf = 0; nf < 8; nf++)
        #pragma unroll
        for (int e = 0; e < 4; e++) Of[nf][e] = 0.f;
    float m_[2] = {-1e30f, -1e30f};
    float l_[2] = {0.f, 0.f};

    issue_kv(0, 0);

    const int NT = SEQ / 64;
    for (int kt = 0; kt < NT; kt++) {
        const int buf = kt & 1;
        __syncthreads();                       // all warps done with buf^1
        if (kt + 1 < NT) { issue_kv(kt + 1, buf ^ 1); cp_wait<1>(); }
        else             { cp_wait<0>(); }
        __syncthreads();                       // tile kt visible

        const float* Ks = sm + FK_OFF + buf * 64 * FW;
        const float* Vs = sm + FV_OFF + buf * 64 * FWV;

        // S = Q @ K^T
        float Sf[8][4];
        #pragma unroll
        for (int nf = 0; nf < 8; nf++)
            #pragma unroll
            for (int e = 0; e < 4; e++) Sf[nf][e] = 0.f;

        #pragma unroll
        for (int s = 0; s < 8; s++) {
            const int k8 = s * 8;
            #pragma unroll
            for (int nf = 0; nf < 8; nf++) {
                uint32_t b0 = __float_as_uint(Ks[(nf * 8 + g) * FW + k8 + t]);
                uint32_t b1 = __float_as_uint(Ks[(nf * 8 + g) * FW + k8 + t + 4]);
                mma_tf32(Sf[nf][0], Sf[nf][1], Sf[nf][2], Sf[nf][3],
                         qf[s][0], qf[s][1], qf[s][2], qf[s][3], b0, b1);
            }
        }

        // Online softmax; P -> smem (warp-private rows)
        #pragma unroll
        for (int r = 0; r < 2; r++) {
            const int e = r * 2;
            float mx = -1e30f;
            #pragma unroll
            for (int nf = 0; nf < 8; nf++)
                mx = fmaxf(mx, fmaxf(Sf[nf][e], Sf[nf][e + 1]));
            mx = fmaxf(mx, __shfl_xor_sync(0xffffffffu, mx, 1));
            mx = fmaxf(mx, __shfl_xor_sync(0xffffffffu, mx, 2));
            const float nm = fmaxf(m_[r], mx);
            const float corr = exp2f(m_[r] - nm);
            float ps = 0.f;
            #pragma unroll
            for (int nf = 0; nf < 8; nf++) {
                Sf[nf][e]     = exp2f(Sf[nf][e] - nm);
                Sf[nf][e + 1] = exp2f(Sf[nf][e + 1] - nm);
                ps += Sf[nf][e] + Sf[nf][e + 1];
            }
            ps += __shfl_xor_sync(0xffffffffu, ps, 1);
            ps += __shfl_xor_sync(0xffffffffu, ps, 2);
            l_[r] = l_[r] * corr + ps;
            m_[r] = nm;
            #pragma unroll
            for (int nf = 0; nf < 8; nf++) {
                Of[nf][e] *= corr; Of[nf][e + 1] *= corr;
            }
            const int row = m0 + g + r * 8;
            #pragma unroll
            for (int nf = 0; nf < 8; nf++) {
                float2 p2 = make_float2(to_tf32(Sf[nf][e]), to_tf32(Sf[nf][e + 1]));
                *reinterpret_cast<float2*>(Ps + row * FW + nf * 8 + 2 * t) = p2;
            }
        }
        __syncwarp();      // P write->read is within-warp only

        // O += P @ V
        #pragma unroll
        for (int s = 0; s < 8; s++) {
            const int k8 = s * 8;
            uint32_t a0 = __float_as_uint(Ps[(m0 + g)     * FW + k8 + t]);
            uint32_t a1 = __float_as_uint(Ps[(m0 + g + 8) * FW + k8 + t]);
            uint32_t a2 = __float_as_uint(Ps[(m0 + g)     * FW + k8 + t + 4]);
            uint32_t a3 = __float_as_uint(Ps[(m0 + g + 8) * FW + k8 + t + 4]);
            #pragma unroll
            for (int nf = 0; nf < 8; nf++) {
                uint32_t b0 = __float_as_uint(Vs[(k8 + t)     * FWV + nf * 8 + g]);
                uint32_t b1 = __float_as_uint(Vs[(k8 + t + 4) * FWV + nf * 8 + g]);
                mma_tf32(Of[nf][0], Of[nf][1], Of[nf][2], Of[nf][3],
                         a0, a1, a2, a3, b0, b1);
            }
        }
    }

    // Normalize, round, store merged heads
    #pragma unroll
    for (int r = 0; r < 2; r++) {
        const float inv = 1.0f / l_[r];
        const long row = (long)b * SEQ + q0 + m0 + g + r * 8;
        const int e = r * 2;
        #pragma unroll
        for (int nf = 0; nf < 8; nf++) {
            float2 o = make_float2(to_tf32(Of[nf][e] * inv),
                                   to_tf32(Of[nf][e + 1] * inv));
            *reinterpret_cast<float2*>(out + row * DIM + h * HD + nf * 8 + 2 * t) = o;
        }
    }
}

// ---------------------------------------------------------------------------
// Elementwise tf32 rounding (weights)
// ---------------------------------------------------------------------------
__global__ void __launch_bounds__(256) round4(
    const float* __restrict__ in, float* __restrict__ out, int n4)
{
    int i = blockIdx.x * 256 + threadIdx.x;
    if (i < n4) {
        float4 v = reinterpret_cast<const float4*>(in)[i];
        v.x = to_tf32(v.x); v.y = to_tf32(v.y);
        v.z = to_tf32(v.z); v.w = to_tf32(v.w);
        reinterpret_cast<float4*>(out)[i] = v;
    }
}

// ---------------------------------------------------------------------------
// LayerNorm (tf32-rounded output)
// ---------------------------------------------------------------------------
__global__ void __launch_bounds__(256) ln_kernel(
    const float* __restrict__ x, const float* __restrict__ g,
    const float* __restrict__ b, float* __restrict__ out)
{
    const int row = blockIdx.x;
    const int tid = threadIdx.x;
    const float4* xr = reinterpret_cast<const float4*>(x + (long)row * DIM);
    float4 v = xr[tid];

    __shared__ float red1[8];
    __shared__ float red2[8];

    float s = v.x + v.y + v.z + v.w;
    #pragma unroll
    for (int off = 16; off; off >>= 1) s += __shfl_xor_sync(0xffffffffu, s, off);
    if ((tid & 31) == 0) red1[tid >> 5] = s;
    __syncthreads();
    float tot = 0.f;
    #pragma unroll
    for (int w = 0; w < 8; w++) tot += red1[w];
    const float mean = tot * (1.0f / DIM);

    float dx = v.x - mean, dy = v.y - mean, dz = v.z - mean, dw = v.w - mean;
    float q = dx * dx + dy * dy + dz * dz + dw * dw;
    #pragma unroll
    for (int off = 16; off; off >>= 1) q += __shfl_xor_sync(0xffffffffu, q, off);
    if ((tid & 31) == 0) red2[tid >> 5] = q;
    __syncthreads();
    float qtot = 0.f;
    #pragma unroll
    for (int w = 0; w < 8; w++) qtot += red2[w];
    const float rstd = rsqrtf(qtot * (1.0f / DIM) + 1e-5f);

    float4 gv = reinterpret_cast<const float4*>(g)[tid];
    float4 bv = reinterpret_cast<const float4*>(b)[tid];
    float4 o;
    o.x = to_tf32(dx * rstd * gv.x + bv.x);
    o.y = to_tf32(dy * rstd * gv.y + bv.y);
    o.z = to_tf32(dz * rstd * gv.z + bv.z);
    o.w = to_tf32(dw * rstd * gv.w + bv.w);
    reinterpret_cast<float4*>(out + (long)row * DIM)[tid] = o;
}

// ---------------------------------------------------------------------------
// Launch
// ---------------------------------------------------------------------------
extern "C" void kernel_launch(void* const* d_in, const int* in_sizes, int n_in,
                              void* d_out, int out_size)
{
    const float* x      = (const float*)d_in[0];
    const float* ln1_g  = (const float*)d_in[1];
    const float* ln1_b  = (const float*)d_in[2];
    const float* w_qkv  = (const float*)d_in[3];
    const float* w_proj = (const float*)d_in[4];
    const float* b_proj = (const float*)d_in[5];
    const float* ln2_g  = (const float*)d_in[6];
    const float* ln2_b  = (const float*)d_in[7];
    const float* w1     = (const float*)d_in[8];
    const float* b1     = (const float*)d_in[9];
    const float* w2     = (const float*)d_in[10];
    const float* b2     = (const float*)d_in[11];
    float* out = (float*)d_out;

    float *h1, *qkv, *attn, *x1, *h2, *hid, *wqkv_r, *wproj_r, *w1_r, *w2_r;
    cudaGetSymbolAddress((void**)&h1,      g_h1);
    cudaGetSymbolAddress((void**)&qkv,     g_qkv);
    cudaGetSymbolAddress((void**)&attn,    g_attn);
    cudaGetSymbolAddress((void**)&x1,      g_x1);
    cudaGetSymbolAddress((void**)&h2,      g_h2);
    cudaGetSymbolAddress((void**)&hid,     g_hid);
    cudaGetSymbolAddress((void**)&wqkv_r,  g_wqkv);
    cudaGetSymbolAddress((void**)&wproj_r, g_wproj);
    cudaGetSymbolAddress((void**)&w1_r,    g_w1);
    cudaGetSymbolAddress((void**)&w2_r,    g_w2);

    cudaFuncSetAttribute(mma_gemm<0,1>, cudaFuncAttributeMaxDynamicSharedMemorySize, GEMM_SMEM);
    cudaFuncSetAttribute(mma_gemm<5,0>, cudaFuncAttributeMaxDynamicSharedMemorySize, GEMM_SMEM);
    cudaFuncSetAttribute(mma_gemm<3,1>, cudaFuncAttributeMaxDynamicSharedMemorySize, GEMM_SMEM);
    cudaFuncSetAttribute(flash_mma,     cudaFuncAttributeMaxDynamicSharedMemorySize, FLASH_SMEM);

    // tf32 weight copies
    round4<<<(DIM * C3 / 4 + 255) / 256, 256>>>(w_qkv,  wqkv_r,  DIM * C3 / 4);
    round4<<<(DIM * DIM / 4 + 255) / 256, 256>>>(w_proj, wproj_r, DIM * DIM / 4);
    round4<<<(DIM * HIDDEN / 4 + 255) / 256, 256>>>(w1,  w1_r,    DIM * HIDDEN / 4);
    round4<<<(HIDDEN * DIM / 4 + 255) / 256, 256>>>(w2,  w2_r,    HIDDEN * DIM / 4);

    // 1) h1 = LN1(x)
    ln_kernel<<<TOK, 256>>>(x, ln1_g, ln1_b, h1);

    // 2) qkv = h1 @ w_qkv
    mma_gemm<0,1><<<dim3(C3 / 128, TOK / 128), 256, GEMM_SMEM>>>(
        h1, wqkv_r, nullptr, nullptr, qkv, TOK, C3, DIM);

    // 3) attention
    flash_mma<<<dim3(SEQ / 128, BATCH * HEADS), 256, FLASH_SMEM>>>(qkv, attn);

    // 4) x1 = x + attn @ w_proj + b_proj
    mma_gemm<5,0><<<dim3(DIM / 128, TOK / 128), 256, GEMM_SMEM>>>(
        attn, wproj_r, b_proj, x, x1, TOK, DIM, DIM);

    // 5) h2 = LN2(x1)
    ln_kernel<<<TOK, 256>>>(x1, ln2_g, ln2_b, h2);

    // 6) hid = gelu(h2 @ w1 + b1)
    mma_gemm<3,1><<<dim3(HIDDEN / 128, TOK / 128), 256, GEMM_SMEM>>>(
        h2, w1_r, b1, nullptr, hid, TOK, HIDDEN, DIM);

    // 7) out = x1 + hid @ w2 + b2
    mma_gemm<5,0><<<dim3(DIM / 128, TOK / 128), 256, GEMM_SMEM>>>(
        hid, w2_r, b2, x1, out, TOK, DIM, HIDDEN);
}

// round 8
// speedup vs baseline: 5.5332x; 1.3468x over previous
#include <cuda_runtime.h>
#include <cuda_fp16.h>
#include <cstdint>
#include <math.h>

// ---------------------------------------------------------------------------
// Problem dims
// ---------------------------------------------------------------------------
#define BATCH   2
#define SEQ     2048
#define TOK     (BATCH * SEQ)      // 4096
#define DIM     1024
#define HEADS   16
#define HD      64
#define HIDDEN  (4 * DIM)          // 4096
#define C3      (3 * DIM)          // 3072

// ---------------------------------------------------------------------------
// Scratch (device globals; no allocations allowed)
// ---------------------------------------------------------------------------
__device__ float  g_qkv [TOK * C3];
__device__ float  g_x1  [TOK * DIM];
__device__ __half g_h1  [TOK * DIM];
__device__ __half g_h2  [TOK * DIM];
__device__ __half g_attn[TOK * DIM];
__device__ __half g_hid [TOK * HIDDEN];
__device__ __half g_wqkvT [C3 * DIM];
__device__ __half g_wprojT[DIM * DIM];
__device__ __half g_w1T   [HIDDEN * DIM];
__device__ __half g_w2T   [DIM * HIDDEN];

// ---------------------------------------------------------------------------
// Helpers
// ---------------------------------------------------------------------------
__device__ __forceinline__ uint32_t smem_u32(const void* p) {
    uint32_t a;
    asm("{ .reg .u64 t; cvta.to.shared.u64 t, %1; cvt.u32.u64 %0, t; }" : "=r"(a) : "l"(p));
    return a;
}
__device__ __forceinline__ float to_tf32(float x) {
    float y; asm("cvt.rna.tf32.f32 %0, %1;" : "=f"(y) : "f"(x)); return y;
}
__device__ __forceinline__ float gelu_erf(float v) {
    return 0.5f * v * (1.0f + erff(v * 0.70710678118654752440f));
}
__device__ __forceinline__ void mma_tf32(
    float& d0, float& d1, float& d2, float& d3,
    uint32_t a0, uint32_t a1, uint32_t a2, uint32_t a3,
    uint32_t b0, uint32_t b1)
{
    asm volatile(
        "mma.sync.aligned.m16n8k8.row.col.f32.tf32.tf32.f32 "
        "{%0,%1,%2,%3}, {%4,%5,%6,%7}, {%8,%9}, {%0,%1,%2,%3};"
        : "+f"(d0), "+f"(d1), "+f"(d2), "+f"(d3)
        : "r"(a0), "r"(a1), "r"(a2), "r"(a3), "r"(b0), "r"(b1));
}
__device__ __forceinline__ void mma_f16(
    float& d0, float& d1, float& d2, float& d3,
    uint32_t a0, uint32_t a1, uint32_t a2, uint32_t a3,
    uint32_t b0, uint32_t b1)
{
    asm volatile(
        "mma.sync.aligned.m16n8k16.row.col.f32.f16.f16.f32 "
        "{%0,%1,%2,%3}, {%4,%5,%6,%7}, {%8,%9}, {%0,%1,%2,%3};"
        : "+f"(d0), "+f"(d1), "+f"(d2), "+f"(d3)
        : "r"(a0), "r"(a1), "r"(a2), "r"(a3), "r"(b0), "r"(b1));
}
__device__ __forceinline__ void cp_async16(uint32_t dst, const void* src) {
    asm volatile("cp.async.cg.shared.global [%0], [%1], 16;" :: "r"(dst), "l"(src));
}
#define CP_COMMIT asm volatile("cp.async.commit_group;")
template <int N>
__device__ __forceinline__ void cp_wait() {
    asm volatile("cp.async.wait_group %0;" :: "n"(N));
}

// ---------------------------------------------------------------------------
// fp16 GEMM: C[M,N] = A[M,K] @ BT[N,K]^T, both fp16 k-major, fp32 accum.
// 128x128 CTA, 8 warps (4m x 2n), warp 32x64, m16n8k16, BK=32, 3-stage.
// EPI: 1=bias, 2=gelu, 4=residual.  HOUT: write C as fp16 (else fp32).
// ---------------------------------------------------------------------------
#define HB_ST 40                        // halves per smem row (32 + 8 pad)
#define HB_STG (128 * HB_ST)
#define GEMMH_SMEM (6 * HB_STG * 2)     // 61440 bytes

template <int EPI, int HOUT>
__global__ void __launch_bounds__(256, 2) mma_gemm_h(
    const __half* __restrict__ A, const __half* __restrict__ BT,
    const float* __restrict__ bias, const float* __restrict__ R,
    void* __restrict__ Cv, int M, int N, int K)
{
    extern __shared__ __half smh[];
    __half* Asm = smh;
    __half* Bsm = smh + 3 * HB_STG;
    const uint32_t a_u32 = smem_u32(Asm);
    const uint32_t b_u32 = smem_u32(Bsm);

    const int tid = threadIdx.x;
    const int lane = tid & 31, warp = tid >> 5;
    const int wy = warp >> 1, wx = warp & 1;
    const int g = lane >> 2, t = lane & 3;
    const int bm = blockIdx.y * 128, bn = blockIdx.x * 128;

    auto issue = [&](int s, int k0) {
        #pragma unroll
        for (int w = 0; w < 2; w++) {
            int id = w * 256 + tid;
            int r = id >> 2, c = (id & 3) << 3;       // 8 halves = 16B
            cp_async16(a_u32 + (uint32_t)(s * HB_STG + r * HB_ST + c) * 2,
                       A + (long)(bm + r) * K + k0 + c);
        }
        #pragma unroll
        for (int w = 0; w < 2; w++) {
            int id = w * 256 + tid;
            int r = id >> 2, c = (id & 3) << 3;
            cp_async16(b_u32 + (uint32_t)(s * HB_STG + r * HB_ST + c) * 2,
                       BT + (long)(bn + r) * K + k0 + c);
        }
        CP_COMMIT;
    };

    float acc[2][8][4];
    #pragma unroll
    for (int i = 0; i < 2; i++)
        #pragma unroll
        for (int j = 0; j < 8; j++)
            #pragma unroll
            for (int e = 0; e < 4; e++) acc[i][j][e] = 0.f;

    const int NK = K >> 5;
    issue(0, 0);
    issue(1, 32);

    for (int it = 0; it < NK; ++it) {
        if (it == NK - 1) { cp_wait<0>(); } else { cp_wait<1>(); }
        __syncthreads();
        if (it + 2 < NK) issue((it + 2) % 3, (it + 2) << 5);

        const uint32_t* as = reinterpret_cast<const uint32_t*>(Asm + (it % 3) * HB_STG);
        const uint32_t* bs = reinterpret_cast<const uint32_t*>(Bsm + (it % 3) * HB_STG);
        #pragma unroll
        for (int k16 = 0; k16 < 32; k16 += 16) {
            uint32_t af[2][4], bf[8][2];
            const int base = (k16 >> 1) + t;
            #pragma unroll
            for (int mf = 0; mf < 2; mf++) {
                const int m0 = wy * 32 + mf * 16;
                af[mf][0] = as[(m0 + g)     * 20 + base];
                af[mf][1] = as[(m0 + g + 8) * 20 + base];
                af[mf][2] = as[(m0 + g)     * 20 + base + 4];
                af[mf][3] = as[(m0 + g + 8) * 20 + base + 4];
            }
            #pragma unroll
            for (int nf = 0; nf < 8; nf++) {
                const int n0 = wx * 64 + nf * 8;
                bf[nf][0] = bs[(n0 + g) * 20 + base];
                bf[nf][1] = bs[(n0 + g) * 20 + base + 4];
            }
            #pragma unroll
            for (int mf = 0; mf < 2; mf++)
                #pragma unroll
                for (int nf = 0; nf < 8; nf++)
                    mma_f16(acc[mf][nf][0], acc[mf][nf][1],
                            acc[mf][nf][2], acc[mf][nf][3],
                            af[mf][0], af[mf][1], af[mf][2], af[mf][3],
                            bf[nf][0], bf[nf][1]);
        }
    }

    #pragma unroll
    for (int mf = 0; mf < 2; mf++) {
        const long row = bm + wy * 32 + mf * 16 + g;
        #pragma unroll
        for (int nf = 0; nf < 8; nf++) {
            const long col = bn + wx * 64 + nf * 8 + t * 2;
            float2 v0 = make_float2(acc[mf][nf][0], acc[mf][nf][1]);
            float2 v1 = make_float2(acc[mf][nf][2], acc[mf][nf][3]);
            if (EPI & 1) {
                const float2 bv = *reinterpret_cast<const float2*>(bias + col);
                v0.x += bv.x; v0.y += bv.y;
                v1.x += bv.x; v1.y += bv.y;
            }
            if (EPI & 2) {
                v0.x = gelu_erf(v0.x); v0.y = gelu_erf(v0.y);
                v1.x = gelu_erf(v1.x); v1.y = gelu_erf(v1.y);
            }
            if (EPI & 4) {
                const float2 r0 = *reinterpret_cast<const float2*>(R + row * N + col);
                const float2 r1 = *reinterpret_cast<const float2*>(R + (row + 8) * N + col);
                v0.x += r0.x; v0.y += r0.y;
                v1.x += r1.x; v1.y += r1.y;
            }
            if (HOUT) {
                __half* C = reinterpret_cast<__half*>(Cv);
                *reinterpret_cast<__half2*>(C + row * N + col) = __floats2half2_rn(v0.x, v0.y);
                *reinterpret_cast<__half2*>(C + (row + 8) * N + col) = __floats2half2_rn(v1.x, v1.y);
            } else {
                float* C = reinterpret_cast<float*>(Cv);
                *reinterpret_cast<float2*>(C + row * N + col) = v0;
                *reinterpret_cast<float2*>(C + (row + 8) * N + col) = v1;
            }
        }
    }
}

// ---------------------------------------------------------------------------
// Flash attention, tf32 mma (R6 structure); epilogue emits fp16 for proj.
// ---------------------------------------------------------------------------
#define FW  68
#define FWV 72
#define FP_OFF 0
#define FK_OFF (128 * FW)
#define FV_OFF (FK_OFF + 2 * 64 * FW)
#define FLASH_SMEM ((FV_OFF + 2 * 64 * FWV) * 4)

__global__ void __launch_bounds__(256, 2) flash_mma(
    const float* __restrict__ qkv, __half* __restrict__ out)
{
    extern __shared__ float sm[];
    float* Ps = sm + FP_OFF;
    const uint32_t k_u32 = smem_u32(sm + FK_OFF);
    const uint32_t v_u32 = smem_u32(sm + FV_OFF);

    const int tid = threadIdx.x;
    const int lane = tid & 31, warp = tid >> 5;
    const int g = lane >> 2, t = lane & 3;
    const int b = blockIdx.y >> 4, h = blockIdx.y & 15;
    const int q0 = blockIdx.x * 128;
    const int m0 = warp * 16;
    const long base = (long)b * SEQ * C3 + h * HD;

    const float qscale = 0.125f * 1.4426950408889634f;
    uint32_t qf[8][4];
    {
        const float* q_lo = qkv + base + (long)(q0 + m0 + g) * C3;
        const float* q_hi = qkv + base + (long)(q0 + m0 + g + 8) * C3;
        #pragma unroll
        for (int s = 0; s < 8; s++) {
            qf[s][0] = __float_as_uint(to_tf32(q_lo[s * 8 + t]     * qscale));
            qf[s][1] = __float_as_uint(to_tf32(q_hi[s * 8 + t]     * qscale));
            qf[s][2] = __float_as_uint(to_tf32(q_lo[s * 8 + t + 4] * qscale));
            qf[s][3] = __float_as_uint(to_tf32(q_hi[s * 8 + t + 4] * qscale));
        }
    }

    auto issue_kv = [&](int kt, int bf) {
        const long kb = base + (long)(kt * 64) * C3;
        #pragma unroll
        for (int i = 0; i < 4; i++) {
            int id = i * 256 + tid;
            int r = id >> 4, c = (id & 15) << 2;
            cp_async16(k_u32 + (uint32_t)(bf * 64 * FW + r * FW + c) * 4,
                       qkv + kb + (long)r * C3 + 1024 + c);
        }
        #pragma unroll
        for (int i = 0; i < 4; i++) {
            int id = i * 256 + tid;
            int r = id >> 4, c = (id & 15) << 2;
            cp_async16(v_u32 + (uint32_t)(bf * 64 * FWV + r * FWV + c) * 4,
                       qkv + kb + (long)r * C3 + 2048 + c);
        }
        CP_COMMIT;
    };

    float Of[8][4];
    #pragma unroll
    for (int nf = 0; nf < 8; nf++)
        #pragma unroll
        for (int e = 0; e < 4; e++) Of[nf][e] = 0.f;
    float m_[2] = {-1e30f, -1e30f};
    float l_[2] = {0.f, 0.f};

    issue_kv(0, 0);

    const int NT = SEQ / 64;
    for (int kt = 0; kt < NT; kt++) {
        const int buf = kt & 1;
        __syncthreads();
        if (kt + 1 < NT) { issue_kv(kt + 1, buf ^ 1); cp_wait<1>(); }
        else             { cp_wait<0>(); }
        __syncthreads();

        const float* Ks = sm + FK_OFF + buf * 64 * FW;
        const float* Vs = sm + FV_OFF + buf * 64 * FWV;

        float Sf[8][4];
        #pragma unroll
        for (int nf = 0; nf < 8; nf++)
            #pragma unroll
            for (int e = 0; e < 4; e++) Sf[nf][e] = 0.f;

        #pragma unroll
        for (int s = 0; s < 8; s++) {
            const int k8 = s * 8;
            #pragma unroll
            for (int nf = 0; nf < 8; nf++) {
                uint32_t b0 = __float_as_uint(Ks[(nf * 8 + g) * FW + k8 + t]);
                uint32_t b1 = __float_as_uint(Ks[(nf * 8 + g) * FW + k8 + t + 4]);
                mma_tf32(Sf[nf][0], Sf[nf][1], Sf[nf][2], Sf[nf][3],
                         qf[s][0], qf[s][1], qf[s][2], qf[s][3], b0, b1);
            }
        }

        #pragma unroll
        for (int r = 0; r < 2; r++) {
            const int e = r * 2;
            float mx = -1e30f;
            #pragma unroll
            for (int nf = 0; nf < 8; nf++)
                mx = fmaxf(mx, fmaxf(Sf[nf][e], Sf[nf][e + 1]));
            mx = fmaxf(mx, __shfl_xor_sync(0xffffffffu, mx, 1));
            mx = fmaxf(mx, __shfl_xor_sync(0xffffffffu, mx, 2));
            const float nm = fmaxf(m_[r], mx);
            const float corr = exp2f(m_[r] - nm);
            float ps = 0.f;
            #pragma unroll
            for (int nf = 0; nf < 8; nf++) {
                Sf[nf][e]     = exp2f(Sf[nf][e] - nm);
                Sf[nf][e + 1] = exp2f(Sf[nf][e + 1] - nm);
                ps += Sf[nf][e] + Sf[nf][e + 1];
            }
            ps += __shfl_xor_sync(0xffffffffu, ps, 1);
            ps += __shfl_xor_sync(0xffffffffu, ps, 2);
            l_[r] = l_[r] * corr + ps;
            m_[r] = nm;
            #pragma unroll
            for (int nf = 0; nf < 8; nf++) {
                Of[nf][e] *= corr; Of[nf][e + 1] *= corr;
            }
            const int row = m0 + g + r * 8;
            #pragma unroll
            for (int nf = 0; nf < 8; nf++) {
                float2 p2 = make_float2(to_tf32(Sf[nf][e]), to_tf32(Sf[nf][e + 1]));
                *reinterpret_cast<float2*>(Ps + row * FW + nf * 8 + 2 * t) = p2;
            }
        }
        __syncwarp();

        #pragma unroll
        for (int s = 0; s < 8; s++) {
            const int k8 = s * 8;
            uint32_t a0 = __float_as_uint(Ps[(m0 + g)     * FW + k8 + t]);
            uint32_t a1 = __float_as_uint(Ps[(m0 + g + 8) * FW + k8 + t]);
            uint32_t a2 = __float_as_uint(Ps[(m0 + g)     * FW + k8 + t + 4]);
            uint32_t a3 = __float_as_uint(Ps[(m0 + g + 8) * FW + k8 + t + 4]);
            #pragma unroll
            for (int nf = 0; nf < 8; nf++) {
                uint32_t b0 = __float_as_uint(Vs[(k8 + t)     * FWV + nf * 8 + g]);
                uint32_t b1 = __float_as_uint(Vs[(k8 + t + 4) * FWV + nf * 8 + g]);
                mma_tf32(Of[nf][0], Of[nf][1], Of[nf][2], Of[nf][3],
                         a0, a1, a2, a3, b0, b1);
            }
        }
    }

    #pragma unroll
    for (int r = 0; r < 2; r++) {
        const float inv = 1.0f / l_[r];
        const long row = (long)b * SEQ + q0 + m0 + g + r * 8;
        const int e = r * 2;
        #pragma unroll
        for (int nf = 0; nf < 8; nf++) {
            *reinterpret_cast<__half2*>(out + row * DIM + h * HD + nf * 8 + 2 * t) =
                __floats2half2_rn(Of[nf][e] * inv, Of[nf][e + 1] * inv);
        }
    }
}

// ---------------------------------------------------------------------------
// Weight transpose + fp16 convert: in fp32 [Rr][Cc] -> out fp16 [Cc][Rr]
// ---------------------------------------------------------------------------
__global__ void __launch_bounds__(256) cvt_T(
    const float* __restrict__ in, __half* __restrict__ out, int Rr, int Cc)
{
    __shared__ float tb[32][33];
    const int c0 = blockIdx.x * 32, r0 = blockIdx.y * 32;
    const int x = threadIdx.x & 31, y = (threadIdx.x >> 5) * 4;
    #pragma unroll
    for (int i = 0; i < 4; i++)
        tb[y + i][x] = in[(long)(r0 + y + i) * Cc + c0 + x];
    __syncthreads();
    #pragma unroll
    for (int i = 0; i < 4; i++)
        out[(long)(c0 + y + i) * Rr + r0 + x] = __float2half(tb[x][y + i]);
}

// ---------------------------------------------------------------------------
// LayerNorm -> fp16
// ---------------------------------------------------------------------------
__global__ void __launch_bounds__(256) ln_h_kernel(
    const float* __restrict__ x, const float* __restrict__ g,
    const float* __restrict__ b, __half* __restrict__ out)
{
    const int row = blockIdx.x;
    const int tid = threadIdx.x;
    float4 v = reinterpret_cast<const float4*>(x + (long)row * DIM)[tid];

    __shared__ float red1[8];
    __shared__ float red2[8];

    float s = v.x + v.y + v.z + v.w;
    #pragma unroll
    for (int off = 16; off; off >>= 1) s += __shfl_xor_sync(0xffffffffu, s, off);
    if ((tid & 31) == 0) red1[tid >> 5] = s;
    __syncthreads();
    float tot = 0.f;
    #pragma unroll
    for (int w = 0; w < 8; w++) tot += red1[w];
    const float mean = tot * (1.0f / DIM);

    float dx = v.x - mean, dy = v.y - mean, dz = v.z - mean, dw = v.w - mean;
    float q = dx * dx + dy * dy + dz * dz + dw * dw;
    #pragma unroll
    for (int off = 16; off; off >>= 1) q += __shfl_xor_sync(0xffffffffu, q, off);
    if ((tid & 31) == 0) red2[tid >> 5] = q;
    __syncthreads();
    float qtot = 0.f;
    #pragma unroll
    for (int w = 0; w < 8; w++) qtot += red2[w];
    const float rstd = rsqrtf(qtot * (1.0f / DIM) + 1e-5f);

    float4 gv = reinterpret_cast<const float4*>(g)[tid];
    float4 bv = reinterpret_cast<const float4*>(b)[tid];
    __half2* op = reinterpret_cast<__half2*>(out + (long)row * DIM) + 2 * tid;
    op[0] = __floats2half2_rn(dx * rstd * gv.x + bv.x, dy * rstd * gv.y + bv.y);
    op[1] = __floats2half2_rn(dz * rstd * gv.z + bv.z, dw * rstd * gv.w + bv.w);
}

// ---------------------------------------------------------------------------
// Launch
// ---------------------------------------------------------------------------
extern "C" void kernel_launch(void* const* d_in, const int* in_sizes, int n_in,
                              void* d_out, int out_size)
{
    const float* x      = (const float*)d_in[0];
    const float* ln1_g  = (const float*)d_in[1];
    const float* ln1_b  = (const float*)d_in[2];
    const float* w_qkv  = (const float*)d_in[3];
    const float* w_proj = (const float*)d_in[4];
    const float* b_proj = (const float*)d_in[5];
    const float* ln2_g  = (const float*)d_in[6];
    const float* ln2_b  = (const float*)d_in[7];
    const float* w1     = (const float*)d_in[8];
    const float* b1     = (const float*)d_in[9];
    const float* w2     = (const float*)d_in[10];
    const float* b2     = (const float*)d_in[11];
    float* out = (float*)d_out;

    float *qkv, *x1;
    __half *h1, *h2, *attn, *hid, *wqkvT, *wprojT, *w1T, *w2T;
    cudaGetSymbolAddress((void**)&qkv,    g_qkv);
    cudaGetSymbolAddress((void**)&x1,     g_x1);
    cudaGetSymbolAddress((void**)&h1,     g_h1);
    cudaGetSymbolAddress((void**)&h2,     g_h2);
    cudaGetSymbolAddress((void**)&attn,   g_attn);
    cudaGetSymbolAddress((void**)&hid,    g_hid);
    cudaGetSymbolAddress((void**)&wqkvT,  g_wqkvT);
    cudaGetSymbolAddress((void**)&wprojT, g_wprojT);
    cudaGetSymbolAddress((void**)&w1T,    g_w1T);
    cudaGetSymbolAddress((void**)&w2T,    g_w2T);

    cudaFuncSetAttribute(mma_gemm_h<0,0>, cudaFuncAttributeMaxDynamicSharedMemorySize, GEMMH_SMEM);
    cudaFuncSetAttribute(mma_gemm_h<5,0>, cudaFuncAttributeMaxDynamicSharedMemorySize, GEMMH_SMEM);
    cudaFuncSetAttribute(mma_gemm_h<3,1>, cudaFuncAttributeMaxDynamicSharedMemorySize, GEMMH_SMEM);
    cudaFuncSetAttribute(flash_mma,       cudaFuncAttributeMaxDynamicSharedMemorySize, FLASH_SMEM);

    // Weight transposes -> fp16 k-major [N][K]
    cvt_T<<<dim3(C3 / 32,     DIM / 32),    256>>>(w_qkv,  wqkvT,  DIM,    C3);
    cvt_T<<<dim3(DIM / 32,    DIM / 32),    256>>>(w_proj, wprojT, DIM,    DIM);
    cvt_T<<<dim3(HIDDEN / 32, DIM / 32),    256>>>(w1,     w1T,    DIM,    HIDDEN);
    cvt_T<<<dim3(DIM / 32,    HIDDEN / 32), 256>>>(w2,     w2T,    HIDDEN, DIM);

    // 1) h1 = LN1(x)  (fp16)
    ln_h_kernel<<<TOK, 256>>>(x, ln1_g, ln1_b, h1);

    // 2) qkv = h1 @ w_qkv  (fp16 MMA, fp32 out)
    mma_gemm_h<0,0><<<dim3(C3 / 128, TOK / 128), 256, GEMMH_SMEM>>>(
        h1, wqkvT, nullptr, nullptr, qkv, TOK, C3, DIM);

    // 3) attention (tf32 flash; fp16 out)
    flash_mma<<<dim3(SEQ / 128, BATCH * HEADS), 256, FLASH_SMEM>>>(qkv, attn);

    // 4) x1 = x + attn @ w_proj + b_proj  (fp32 residual)
    mma_gemm_h<5,0><<<dim3(DIM / 128, TOK / 128), 256, GEMMH_SMEM>>>(
        attn, wprojT, b_proj, x, x1, TOK, DIM, DIM);

    // 5) h2 = LN2(x1)  (fp16)
    ln_h_kernel<<<TOK, 256>>>(x1, ln2_g, ln2_b, h2);

    // 6) hid = gelu(h2 @ w1 + b1)  (fp16 out)
    mma_gemm_h<3,1><<<dim3(HIDDEN / 128, TOK / 128), 256, GEMMH_SMEM>>>(
        h2, w1T, b1, nullptr, hid, TOK, HIDDEN, DIM);

    // 7) out = x1 + hid @ w2 + b2  (fp32 residual)
    mma_gemm_h<5,0><<<dim3(DIM / 128, TOK / 128), 256, GEMMH_SMEM>>>(
        hid, w2T, b2, x1, out, TOK, DIM, HIDDEN);
}

// round 10
// speedup vs baseline: 6.7192x; 1.2143x over previous
#include <cuda_runtime.h>
#include <cuda_fp16.h>
#include <cstdint>
#include <math.h>

// ---------------------------------------------------------------------------
// Problem dims
// ---------------------------------------------------------------------------
#define BATCH   2
#define SEQ     2048
#define TOK     (BATCH * SEQ)      // 4096
#define DIM     1024
#define HEADS   16
#define HD      64
#define HIDDEN  (4 * DIM)          // 4096
#define C3      (3 * DIM)          // 3072

// ---------------------------------------------------------------------------
// Scratch (device globals; no allocations allowed)
// ---------------------------------------------------------------------------
__device__ float  g_x1  [TOK * DIM];
__device__ __half g_qkvh[TOK * C3];
__device__ __half g_h1  [TOK * DIM];
__device__ __half g_h2  [TOK * DIM];
__device__ __half g_attn[TOK * DIM];
__device__ __half g_hid [TOK * HIDDEN];
__device__ __half g_wqkvT [C3 * DIM];
__device__ __half g_wprojT[DIM * DIM];
__device__ __half g_w1T   [HIDDEN * DIM];
__device__ __half g_w2T   [DIM * HIDDEN];

// ---------------------------------------------------------------------------
// Helpers
// ---------------------------------------------------------------------------
__device__ __forceinline__ uint32_t smem_u32(const void* p) {
    uint32_t a;
    asm("{ .reg .u64 t; cvta.to.shared.u64 t, %1; cvt.u32.u64 %0, t; }" : "=r"(a) : "l"(p));
    return a;
}
__device__ __forceinline__ float gelu_erf(float v) {
    return 0.5f * v * (1.0f + erff(v * 0.70710678118654752440f));
}
// pack two fp32 -> fp16x2 in one instruction (hi = b, lo = a)
__device__ __forceinline__ uint32_t pack_f16x2(float a, float b) {
    uint32_t r;
    asm("cvt.rn.f16x2.f32 %0, %1, %2;" : "=r"(r) : "f"(b), "f"(a));
    return r;
}
__device__ __forceinline__ void mma_f16(
    float& d0, float& d1, float& d2, float& d3,
    uint32_t a0, uint32_t a1, uint32_t a2, uint32_t a3,
    uint32_t b0, uint32_t b1)
{
    asm volatile(
        "mma.sync.aligned.m16n8k16.row.col.f32.f16.f16.f32 "
        "{%0,%1,%2,%3}, {%4,%5,%6,%7}, {%8,%9}, {%0,%1,%2,%3};"
        : "+f"(d0), "+f"(d1), "+f"(d2), "+f"(d3)
        : "r"(a0), "r"(a1), "r"(a2), "r"(a3), "r"(b0), "r"(b1));
}
__device__ __forceinline__ void ldsm_x4_t(
    uint32_t& r0, uint32_t& r1, uint32_t& r2, uint32_t& r3, uint32_t addr)
{
    asm volatile("ldmatrix.sync.aligned.m8n8.x4.trans.shared.b16 {%0,%1,%2,%3}, [%4];"
        : "=r"(r0), "=r"(r1), "=r"(r2), "=r"(r3) : "r"(addr));
}
__device__ __forceinline__ void cp_async16(uint32_t dst, const void* src) {
    asm volatile("cp.async.cg.shared.global [%0], [%1], 16;" :: "r"(dst), "l"(src));
}
#define CP_COMMIT asm volatile("cp.async.commit_group;")
template <int N>
__device__ __forceinline__ void cp_wait() {
    asm volatile("cp.async.wait_group %0;" :: "n"(N));
}

// ---------------------------------------------------------------------------
// fp16 GEMM (R8 structure): C = A @ BT^T, fp32 accum.
// 128x128 CTA, 8 warps (4x2), warp 32x64, m16n8k16, BK=32, 3-stage.
// EPI: 1=bias, 2=gelu, 4=residual.  HOUT: write fp16 (else fp32).
// ---------------------------------------------------------------------------
#define HB_ST 40
#define HB_STG (128 * HB_ST)
#define GEMMH_SMEM (6 * HB_STG * 2)     // 61440 bytes

template <int EPI, int HOUT>
__global__ void __launch_bounds__(256, 2) mma_gemm_h(
    const __half* __restrict__ A, const __half* __restrict__ BT,
    const float* __restrict__ bias, const float* __restrict__ R,
    void* __restrict__ Cv, int M, int N, int K)
{
    extern __shared__ __half smh[];
    __half* Asm = smh;
    __half* Bsm = smh + 3 * HB_STG;
    const uint32_t a_u32 = smem_u32(Asm);
    const uint32_t b_u32 = smem_u32(Bsm);

    const int tid = threadIdx.x;
    const int lane = tid & 31, warp = tid >> 5;
    const int wy = warp >> 1, wx = warp & 1;
    const int g = lane >> 2, t = lane & 3;
    const int bm = blockIdx.y * 128, bn = blockIdx.x * 128;

    auto issue = [&](int s, int k0) {
        #pragma unroll
        for (int w = 0; w < 2; w++) {
            int id = w * 256 + tid;
            int r = id >> 2, c = (id & 3) << 3;
            cp_async16(a_u32 + (uint32_t)(s * HB_STG + r * HB_ST + c) * 2,
                       A + (long)(bm + r) * K + k0 + c);
        }
        #pragma unroll
        for (int w = 0; w < 2; w++) {
            int id = w * 256 + tid;
            int r = id >> 2, c = (id & 3) << 3;
            cp_async16(b_u32 + (uint32_t)(s * HB_STG + r * HB_ST + c) * 2,
                       BT + (long)(bn + r) * K + k0 + c);
        }
        CP_COMMIT;
    };

    float acc[2][8][4];
    #pragma unroll
    for (int i = 0; i < 2; i++)
        #pragma unroll
        for (int j = 0; j < 8; j++)
            #pragma unroll
            for (int e = 0; e < 4; e++) acc[i][j][e] = 0.f;

    const int NK = K >> 5;
    issue(0, 0);
    issue(1, 32);

    for (int it = 0; it < NK; ++it) {
        if (it == NK - 1) { cp_wait<0>(); } else { cp_wait<1>(); }
        __syncthreads();
        if (it + 2 < NK) issue((it + 2) % 3, (it + 2) << 5);

        const uint32_t* as = reinterpret_cast<const uint32_t*>(Asm + (it % 3) * HB_STG);
        const uint32_t* bs = reinterpret_cast<const uint32_t*>(Bsm + (it % 3) * HB_STG);
        #pragma unroll
        for (int k16 = 0; k16 < 32; k16 += 16) {
            uint32_t af[2][4], bf[8][2];
            const int base = (k16 >> 1) + t;
            #pragma unroll
            for (int mf = 0; mf < 2; mf++) {
                const int m0 = wy * 32 + mf * 16;
                af[mf][0] = as[(m0 + g)     * 20 + base];
                af[mf][1] = as[(m0 + g + 8) * 20 + base];
                af[mf][2] = as[(m0 + g)     * 20 + base + 4];
                af[mf][3] = as[(m0 + g + 8) * 20 + base + 4];
            }
            #pragma unroll
            for (int nf = 0; nf < 8; nf++) {
                const int n0 = wx * 64 + nf * 8;
                bf[nf][0] = bs[(n0 + g) * 20 + base];
                bf[nf][1] = bs[(n0 + g) * 20 + base + 4];
            }
            #pragma unroll
            for (int mf = 0; mf < 2; mf++)
                #pragma unroll
                for (int nf = 0; nf < 8; nf++)
                    mma_f16(acc[mf][nf][0], acc[mf][nf][1],
                            acc[mf][nf][2], acc[mf][nf][3],
                            af[mf][0], af[mf][1], af[mf][2], af[mf][3],
                            bf[nf][0], bf[nf][1]);
        }
    }

    #pragma unroll
    for (int mf = 0; mf < 2; mf++) {
        const long row = bm + wy * 32 + mf * 16 + g;
        #pragma unroll
        for (int nf = 0; nf < 8; nf++) {
            const long col = bn + wx * 64 + nf * 8 + t * 2;
            float2 v0 = make_float2(acc[mf][nf][0], acc[mf][nf][1]);
            float2 v1 = make_float2(acc[mf][nf][2], acc[mf][nf][3]);
            if (EPI & 1) {
                const float2 bv = *reinterpret_cast<const float2*>(bias + col);
                v0.x += bv.x; v0.y += bv.y;
                v1.x += bv.x; v1.y += bv.y;
            }
            if (EPI & 2) {
                v0.x = gelu_erf(v0.x); v0.y = gelu_erf(v0.y);
                v1.x = gelu_erf(v1.x); v1.y = gelu_erf(v1.y);
            }
            if (EPI & 4) {
                const float2 r0 = *reinterpret_cast<const float2*>(R + row * N + col);
                const float2 r1 = *reinterpret_cast<const float2*>(R + (row + 8) * N + col);
                v0.x += r0.x; v0.y += r0.y;
                v1.x += r1.x; v1.y += r1.y;
            }
            if (HOUT) {
                __half* C = reinterpret_cast<__half*>(Cv);
                *reinterpret_cast<uint32_t*>(C + row * N + col) = pack_f16x2(v0.x, v0.y);
                *reinterpret_cast<uint32_t*>(C + (row + 8) * N + col) = pack_f16x2(v1.x, v1.y);
            } else {
                float* C = reinterpret_cast<float*>(Cv);
                *reinterpret_cast<float2*>(C + row * N + col) = v0;
                *reinterpret_cast<float2*>(C + (row + 8) * N + col) = v1;
            }
        }
    }
}

// ---------------------------------------------------------------------------
// fp16 flash attention (FA2 style): 128 q-rows/CTA, 8 warps x 16 rows.
// Q in registers; K/V fp16 double-buffered; P stays in registers
// (S C-frags -> PV A-frags); V via ldmatrix.x4.trans.
// ---------------------------------------------------------------------------
#define KVST 72                         // halves per K/V row (64 + 8 pad)
#define KVBUF (64 * KVST)               // halves per buffer
#define FK_OFF 0
#define FV_OFF (2 * KVBUF)
#define FLASH_SMEM (4 * KVBUF * 2)      // 36864 bytes

__global__ void __launch_bounds__(256, 2) flash_h(
    const __half* __restrict__ qkv, __half* __restrict__ out)
{
    extern __shared__ __half smh[];
    const uint32_t k_su = smem_u32(smh + FK_OFF);
    const uint32_t v_su = smem_u32(smh + FV_OFF);

    const int tid = threadIdx.x;
    const int lane = tid & 31, warp = tid >> 5;
    const int g = lane >> 2, t = lane & 3;
    const int lm = lane >> 3, lr = lane & 7;       // ldmatrix addressing
    const int b = blockIdx.y >> 4, h = blockIdx.y & 15;
    const int q0 = blockIdx.x * 128;
    const int m0 = warp * 16;
    const long base = (long)b * SEQ * C3 + h * HD;

    // Q fragments from global fp16 (uint32 = half2), 16 regs
    uint32_t qf[4][4];
    {
        const uint32_t* q_lo = reinterpret_cast<const uint32_t*>(
            qkv + base + (long)(q0 + m0 + g) * C3);
        const uint32_t* q_hi = reinterpret_cast<const uint32_t*>(
            qkv + base + (long)(q0 + m0 + g + 8) * C3);
        #pragma unroll
        for (int s = 0; s < 4; s++) {
            qf[s][0] = q_lo[8 * s + t];
            qf[s][1] = q_hi[8 * s + t];
            qf[s][2] = q_lo[8 * s + t + 4];
            qf[s][3] = q_hi[8 * s + t + 4];
        }
    }

    auto issue_kv = [&](int kt, int bf) {
        const long kb = base + (long)(kt * 64) * C3;
        #pragma unroll
        for (int i = 0; i < 2; i++) {
            int id = i * 256 + tid;
            int r = id >> 3, c = (id & 7) << 3;     // 8 halves = 16B
            cp_async16(k_su + (uint32_t)(bf * KVBUF + r * KVST + c) * 2,
                       qkv + kb + (long)r * C3 + 1024 + c);
        }
        #pragma unroll
        for (int i = 0; i < 2; i++) {
            int id = i * 256 + tid;
            int r = id >> 3, c = (id & 7) << 3;
            cp_async16(v_su + (uint32_t)(bf * KVBUF + r * KVST + c) * 2,
                       qkv + kb + (long)r * C3 + 2048 + c);
        }
        CP_COMMIT;
    };

    float Of[8][4];
    #pragma unroll
    for (int nf = 0; nf < 8; nf++)
        #pragma unroll
        for (int e = 0; e < 4; e++) Of[nf][e] = 0.f;
    float m_[2] = {-1e30f, -1e30f};
    float l_[2] = {0.f, 0.f};
    const float sscale = 0.125f * 1.4426950408889634f;   // applied to S

    issue_kv(0, 0);

    const int NT = SEQ / 64;
    for (int kt = 0; kt < NT; kt++) {
        const int buf = kt & 1;
        __syncthreads();
        if (kt + 1 < NT) { issue_kv(kt + 1, buf ^ 1); cp_wait<1>(); }
        else             { cp_wait<0>(); }
        __syncthreads();

        const uint32_t* Ku = reinterpret_cast<const uint32_t*>(smh + FK_OFF + buf * KVBUF);

        // S = Q @ K^T  (fp16 mma, fp32 accum)
        float Sf[8][4];
        #pragma unroll
        for (int nf = 0; nf < 8; nf++)
            #pragma unroll
            for (int e = 0; e < 4; e++) Sf[nf][e] = 0.f;

        #pragma unroll
        for (int s = 0; s < 4; s++) {
            const int kb32 = 8 * s + t;         // uint32 col index
            #pragma unroll
            for (int nf = 0; nf < 8; nf++) {
                uint32_t b0 = Ku[(nf * 8 + g) * 36 + kb32];
                uint32_t b1 = Ku[(nf * 8 + g) * 36 + kb32 + 4];
                mma_f16(Sf[nf][0], Sf[nf][1], Sf[nf][2], Sf[nf][3],
                        qf[s][0], qf[s][1], qf[s][2], qf[s][3], b0, b1);
            }
        }
        // scale into exp2 domain
        #pragma unroll
        for (int nf = 0; nf < 8; nf++)
            #pragma unroll
            for (int e = 0; e < 4; e++) Sf[nf][e] *= sscale;

        // Online softmax (rows g: e=0,1 | rows g+8: e=2,3)
        #pragma unroll
        for (int r = 0; r < 2; r++) {
            const int e = r * 2;
            float mx = -1e30f;
            #pragma unroll
            for (int nf = 0; nf < 8; nf++)
                mx = fmaxf(mx, fmaxf(Sf[nf][e], Sf[nf][e + 1]));
            mx = fmaxf(mx, __shfl_xor_sync(0xffffffffu, mx, 1));
            mx = fmaxf(mx, __shfl_xor_sync(0xffffffffu, mx, 2));
            const float nm = fmaxf(m_[r], mx);
            const float corr = exp2f(m_[r] - nm);
            float ps = 0.f;
            #pragma unroll
            for (int nf = 0; nf < 8; nf++) {
                Sf[nf][e]     = exp2f(Sf[nf][e] - nm);
                Sf[nf][e + 1] = exp2f(Sf[nf][e + 1] - nm);
                ps += Sf[nf][e] + Sf[nf][e + 1];
            }
            ps += __shfl_xor_sync(0xffffffffu, ps, 1);
            ps += __shfl_xor_sync(0xffffffffu, ps, 2);
            l_[r] = l_[r] * corr + ps;
            m_[r] = nm;
            #pragma unroll
            for (int nf = 0; nf < 8; nf++) {
                Of[nf][e] *= corr; Of[nf][e + 1] *= corr;
            }
        }

        // O += P @ V : P converted in-register to A-fragments; V via ldmatrix.trans
        const uint32_t v_base = v_su + (uint32_t)(buf * KVBUF) * 2;
        #pragma unroll
        for (int s = 0; s < 4; s++) {
            uint32_t pa0 = pack_f16x2(Sf[2*s][0],   Sf[2*s][1]);
            uint32_t pa1 = pack_f16x2(Sf[2*s][2],   Sf[2*s][3]);
            uint32_t pa2 = pack_f16x2(Sf[2*s+1][0], Sf[2*s+1][1]);
            uint32_t pa3 = pack_f16x2(Sf[2*s+1][2], Sf[2*s+1][3]);
            #pragma unroll
            for (int np = 0; np < 4; np++) {
                uint32_t b0a, b1a, b0b, b1b;
                const uint32_t addr = v_base +
                    (uint32_t)((16 * s + (lm & 1) * 8 + lr) * KVST + 16 * np + (lm >> 1) * 8) * 2;
                ldsm_x4_t(b0a, b1a, b0b, b1b, addr);
                mma_f16(Of[2*np][0],   Of[2*np][1],   Of[2*np][2],   Of[2*np][3],
                        pa0, pa1, pa2, pa3, b0a, b1a);
                mma_f16(Of[2*np+1][0], Of[2*np+1][1], Of[2*np+1][2], Of[2*np+1][3],
                        pa0, pa1, pa2, pa3, b0b, b1b);
            }
        }
    }

    // Normalize, write fp16 merged heads
    #pragma unroll
    for (int r = 0; r < 2; r++) {
        const float inv = 1.0f / l_[r];
        const long row = (long)b * SEQ + q0 + m0 + g + r * 8;
        const int e = r * 2;
        #pragma unroll
        for (int nf = 0; nf < 8; nf++) {
            *reinterpret_cast<uint32_t*>(out + row * DIM + h * HD + nf * 8 + 2 * t) =
                pack_f16x2(Of[nf][e] * inv, Of[nf][e + 1] * inv);
        }
    }
}

// ---------------------------------------------------------------------------
// Weight transpose + fp16 convert
// ---------------------------------------------------------------------------
__global__ void __launch_bounds__(256) cvt_T(
    const float* __restrict__ in, __half* __restrict__ out, int Rr, int Cc)
{
    __shared__ float tb[32][33];
    const int c0 = blockIdx.x * 32, r0 = blockIdx.y * 32;
    const int x = threadIdx.x & 31, y = (threadIdx.x >> 5) * 4;
    #pragma unroll
    for (int i = 0; i < 4; i++)
        tb[y + i][x] = in[(long)(r0 + y + i) * Cc + c0 + x];
    __syncthreads();
    #pragma unroll
    for (int i = 0; i < 4; i++)
        out[(long)(c0 + y + i) * Rr + r0 + x] = __float2half(tb[x][y + i]);
}

// ---------------------------------------------------------------------------
// LayerNorm -> fp16
// ---------------------------------------------------------------------------
__global__ void __launch_bounds__(256) ln_h_kernel(
    const float* __restrict__ x, const float* __restrict__ g,
    const float* __restrict__ b, __half* __restrict__ out)
{
    const int row = blockIdx.x;
    const int tid = threadIdx.x;
    float4 v = reinterpret_cast<const float4*>(x + (long)row * DIM)[tid];

    __shared__ float red1[8];
    __shared__ float red2[8];

    float s = v.x + v.y + v.z + v.w;
    #pragma unroll
    for (int off = 16; off; off >>= 1) s += __shfl_xor_sync(0xffffffffu, s, off);
    if ((tid & 31) == 0) red1[tid >> 5] = s;
    __syncthreads();
    float tot = 0.f;
    #pragma unroll
    for (int w = 0; w < 8; w++) tot += red1[w];
    const float mean = tot * (1.0f / DIM);

    float dx = v.x - mean, dy = v.y - mean, dz = v.z - mean, dw = v.w - mean;
    float q = dx * dx + dy * dy + dz * dz + dw * dw;
    #pragma unroll
    for (int off = 16; off; off >>= 1) q += __shfl_xor_sync(0xffffffffu, q, off);
    if ((tid & 31) == 0) red2[tid >> 5] = q;
    __syncthreads();
    float qtot = 0.f;
    #pragma unroll
    for (int w = 0; w < 8; w++) qtot += red2[w];
    const float rstd = rsqrtf(qtot * (1.0f / DIM) + 1e-5f);

    float4 gv = reinterpret_cast<const float4*>(g)[tid];
    float4 bv = reinterpret_cast<const float4*>(b)[tid];
    uint32_t* op = reinterpret_cast<uint32_t*>(out + (long)row * DIM) + 2 * tid;
    op[0] = pack_f16x2(dx * rstd * gv.x + bv.x, dy * rstd * gv.y + bv.y);
    op[1] = pack_f16x2(dz * rstd * gv.z + bv.z, dw * rstd * gv.w + bv.w);
}

// ---------------------------------------------------------------------------
// Launch
// ---------------------------------------------------------------------------
extern "C" void kernel_launch(void* const* d_in, const int* in_sizes, int n_in,
                              void* d_out, int out_size)
{
    const float* x      = (const float*)d_in[0];
    const float* ln1_g  = (const float*)d_in[1];
    const float* ln1_b  = (const float*)d_in[2];
    const float* w_qkv  = (const float*)d_in[3];
    const float* w_proj = (const float*)d_in[4];
    const float* b_proj = (const float*)d_in[5];
    const float* ln2_g  = (const float*)d_in[6];
    const float* ln2_b  = (const float*)d_in[7];
    const float* w1     = (const float*)d_in[8];
    const float* b1     = (const float*)d_in[9];
    const float* w2     = (const float*)d_in[10];
    const float* b2     = (const float*)d_in[11];
    float* out = (float*)d_out;

    float *x1;
    __half *qkvh, *h1, *h2, *attn, *hid, *wqkvT, *wprojT, *w1T, *w2T;
    cudaGetSymbolAddress((void**)&x1,     g_x1);
    cudaGetSymbolAddress((void**)&qkvh,   g_qkvh);
    cudaGetSymbolAddress((void**)&h1,     g_h1);
    cudaGetSymbolAddress((void**)&h2,     g_h2);
    cudaGetSymbolAddress((void**)&attn,   g_attn);
    cudaGetSymbolAddress((void**)&hid,    g_hid);
    cudaGetSymbolAddress((void**)&wqkvT,  g_wqkvT);
    cudaGetSymbolAddress((void**)&wprojT, g_wprojT);
    cudaGetSymbolAddress((void**)&w1T,    g_w1T);
    cudaGetSymbolAddress((void**)&w2T,    g_w2T);

    cudaFuncSetAttribute(mma_gemm_h<0,1>, cudaFuncAttributeMaxDynamicSharedMemorySize, GEMMH_SMEM);
    cudaFuncSetAttribute(mma_gemm_h<5,0>, cudaFuncAttributeMaxDynamicSharedMemorySize, GEMMH_SMEM);
    cudaFuncSetAttribute(mma_gemm_h<3,1>, cudaFuncAttributeMaxDynamicSharedMemorySize, GEMMH_SMEM);
    cudaFuncSetAttribute(flash_h,         cudaFuncAttributeMaxDynamicSharedMemorySize, FLASH_SMEM);

    // Weight transposes -> fp16 k-major [N][K]
    cvt_T<<<dim3(C3 / 32,     DIM / 32),    256>>>(w_qkv,  wqkvT,  DIM,    C3);
    cvt_T<<<dim3(DIM / 32,    DIM / 32),    256>>>(w_proj, wprojT, DIM,    DIM);
    cvt_T<<<dim3(HIDDEN / 32, DIM / 32),    256>>>(w1,     w1T,    DIM,    HIDDEN);
    cvt_T<<<dim3(DIM / 32,    HIDDEN / 32), 256>>>(w2,     w2T,    HIDDEN, DIM);

    // 1) h1 = LN1(x)  (fp16)
    ln_h_kernel<<<TOK, 256>>>(x, ln1_g, ln1_b, h1);

    // 2) qkvh = h1 @ w_qkv  (fp16 out)
    mma_gemm_h<0,1><<<dim3(C3 / 128, TOK / 128), 256, GEMMH_SMEM>>>(
        h1, wqkvT, nullptr, nullptr, qkvh, TOK, C3, DIM);

    // 3) attention (fp16 flash, register P)
    flash_h<<<dim3(SEQ / 128, BATCH * HEADS), 256, FLASH_SMEM>>>(qkvh, attn);

    // 4) x1 = x + attn @ w_proj + b_proj  (fp32 residual)
    mma_gemm_h<5,0><<<dim3(DIM / 128, TOK / 128), 256, GEMMH_SMEM>>>(
        attn, wprojT, b_proj, x, x1, TOK, DIM, DIM);

    // 5) h2 = LN2(x1)  (fp16)
    ln_h_kernel<<<TOK, 256>>>(x1, ln2_g, ln2_b, h2);

    // 6) hid = gelu(h2 @ w1 + b1)  (fp16 out)
    mma_gemm_h<3,1><<<dim3(HIDDEN / 128, TOK / 128), 256, GEMMH_SMEM>>>(
        h2, w1T, b1, nullptr, hid, TOK, HIDDEN, DIM);

    // 7) out = x1 + hid @ w2 + b2  (fp32 residual)
    mma_gemm_h<5,0><<<dim3(DIM / 128, TOK / 128), 256, GEMMH_SMEM>>>(
        hid, w2T, b2, x1, out, TOK, DIM, HIDDEN);
}

// round 11
// speedup vs baseline: 7.2932x; 1.0854x over previous
#include <cuda_runtime.h>
#include <cuda_fp16.h>
#include <cstdint>
#include <math.h>

// ---------------------------------------------------------------------------
// Problem dims
// ---------------------------------------------------------------------------
#define BATCH   2
#define SEQ     2048
#define TOK     (BATCH * SEQ)      // 4096
#define DIM     1024
#define HEADS   16
#define HD      64
#define HIDDEN  (4 * DIM)          // 4096
#define C3      (3 * DIM)          // 3072

// ---------------------------------------------------------------------------
// Scratch (device globals; no allocations allowed)
// ---------------------------------------------------------------------------
__device__ float  g_x1  [TOK * DIM];
__device__ __half g_qkvh[TOK * C3];
__device__ __half g_h1  [TOK * DIM];
__device__ __half g_h2  [TOK * DIM];
__device__ __half g_attn[TOK * DIM];
__device__ __half g_hid [TOK * HIDDEN];
__device__ __half g_wqkvT [C3 * DIM];
__device__ __half g_wprojT[DIM * DIM];
__device__ __half g_w1T   [HIDDEN * DIM];
__device__ __half g_w2T   [DIM * HIDDEN];

// ---------------------------------------------------------------------------
// Helpers
// ---------------------------------------------------------------------------
__device__ __forceinline__ uint32_t smem_u32(const void* p) {
    uint32_t a;
    asm("{ .reg .u64 t; cvta.to.shared.u64 t, %1; cvt.u32.u64 %0, t; }" : "=r"(a) : "l"(p));
    return a;
}
__device__ __forceinline__ float gelu_erf(float v) {
    return 0.5f * v * (1.0f + erff(v * 0.70710678118654752440f));
}
__device__ __forceinline__ uint32_t pack_f16x2(float a, float b) {
    uint32_t r;
    asm("cvt.rn.f16x2.f32 %0, %1, %2;" : "=r"(r) : "f"(b), "f"(a));
    return r;
}
__device__ __forceinline__ void mma_f16(
    float& d0, float& d1, float& d2, float& d3,
    uint32_t a0, uint32_t a1, uint32_t a2, uint32_t a3,
    uint32_t b0, uint32_t b1)
{
    asm volatile(
        "mma.sync.aligned.m16n8k16.row.col.f32.f16.f16.f32 "
        "{%0,%1,%2,%3}, {%4,%5,%6,%7}, {%8,%9}, {%0,%1,%2,%3};"
        : "+f"(d0), "+f"(d1), "+f"(d2), "+f"(d3)
        : "r"(a0), "r"(a1), "r"(a2), "r"(a3), "r"(b0), "r"(b1));
}
__device__ __forceinline__ void ldsm_x4(
    uint32_t& r0, uint32_t& r1, uint32_t& r2, uint32_t& r3, uint32_t addr)
{
    asm volatile("ldmatrix.sync.aligned.m8n8.x4.shared.b16 {%0,%1,%2,%3}, [%4];"
        : "=r"(r0), "=r"(r1), "=r"(r2), "=r"(r3) : "r"(addr));
}
__device__ __forceinline__ void ldsm_x4_t(
    uint32_t& r0, uint32_t& r1, uint32_t& r2, uint32_t& r3, uint32_t addr)
{
    asm volatile("ldmatrix.sync.aligned.m8n8.x4.trans.shared.b16 {%0,%1,%2,%3}, [%4];"
        : "=r"(r0), "=r"(r1), "=r"(r2), "=r"(r3) : "r"(addr));
}
__device__ __forceinline__ void cp_async16(uint32_t dst, const void* src) {
    asm volatile("cp.async.cg.shared.global [%0], [%1], 16;" :: "r"(dst), "l"(src));
}
#define CP_COMMIT asm volatile("cp.async.commit_group;")
template <int N>
__device__ __forceinline__ void cp_wait() {
    asm volatile("cp.async.wait_group %0;" :: "n"(N));
}

// ---------------------------------------------------------------------------
// fp16 GEMM: C = A @ BT^T, fp32 accum. 128x128 CTA, 8 warps (4x2),
// warp 32x64, m16n8k16, BK=32, 3-stage cp.async, ldmatrix fragments.
// EPI: 1=bias, 2=gelu, 4=residual.  HOUT: write fp16 (else fp32).
// ---------------------------------------------------------------------------
#define HB_ST 40
#define HB_STG (128 * HB_ST)
#define GEMMH_SMEM (6 * HB_STG * 2)     // 61440 bytes

template <int EPI, int HOUT>
__global__ void __launch_bounds__(256, 2) mma_gemm_h(
    const __half* __restrict__ A, const __half* __restrict__ BT,
    const float* __restrict__ bias, const float* __restrict__ R,
    void* __restrict__ Cv, int M, int N, int K)
{
    extern __shared__ __half smh[];
    __half* Asm = smh;
    __half* Bsm = smh + 3 * HB_STG;
    const uint32_t a_u32 = smem_u32(Asm);
    const uint32_t b_u32 = smem_u32(Bsm);

    const int tid = threadIdx.x;
    const int lane = tid & 31, warp = tid >> 5;
    const int wy = warp >> 1, wx = warp & 1;
    const int g = lane >> 2, t = lane & 3;
    const int bm = blockIdx.y * 128, bn = blockIdx.x * 128;

    // ldmatrix lane-relative byte offsets (within a stage)
    uint32_t aoff[2], boff[4];
    #pragma unroll
    for (int mf = 0; mf < 2; mf++)
        aoff[mf] = (uint32_t)(((wy * 32 + mf * 16 + (lane & 15)) * HB_ST
                               + (lane >> 4) * 8) * 2);
    #pragma unroll
    for (int j = 0; j < 4; j++)
        boff[j] = (uint32_t)(((wx * 64 + j * 16 + ((lane >> 4) & 1) * 8 + (lane & 7)) * HB_ST
                              + ((lane >> 3) & 1) * 8) * 2);

    auto issue = [&](int s, int k0) {
        #pragma unroll
        for (int w = 0; w < 2; w++) {
            int id = w * 256 + tid;
            int r = id >> 2, c = (id & 3) << 3;
            cp_async16(a_u32 + (uint32_t)(s * HB_STG + r * HB_ST + c) * 2,
                       A + (long)(bm + r) * K + k0 + c);
        }
        #pragma unroll
        for (int w = 0; w < 2; w++) {
            int id = w * 256 + tid;
            int r = id >> 2, c = (id & 3) << 3;
            cp_async16(b_u32 + (uint32_t)(s * HB_STG + r * HB_ST + c) * 2,
                       BT + (long)(bn + r) * K + k0 + c);
        }
        CP_COMMIT;
    };

    float acc[2][8][4];
    #pragma unroll
    for (int i = 0; i < 2; i++)
        #pragma unroll
        for (int j = 0; j < 8; j++)
            #pragma unroll
            for (int e = 0; e < 4; e++) acc[i][j][e] = 0.f;

    const int NK = K >> 5;
    issue(0, 0);
    issue(1, 32);

    for (int it = 0; it < NK; ++it) {
        if (it == NK - 1) { cp_wait<0>(); } else { cp_wait<1>(); }
        __syncthreads();
        if (it + 2 < NK) issue((it + 2) % 3, (it + 2) << 5);

        const uint32_t a_st = a_u32 + (uint32_t)((it % 3) * HB_STG) * 2;
        const uint32_t b_st = b_u32 + (uint32_t)((it % 3) * HB_STG) * 2;
        #pragma unroll
        for (int k16 = 0; k16 < 32; k16 += 16) {
            uint32_t af[2][4], bf[8][2];
            #pragma unroll
            for (int mf = 0; mf < 2; mf++)
                ldsm_x4(af[mf][0], af[mf][1], af[mf][2], af[mf][3],
                        a_st + aoff[mf] + k16 * 2);
            #pragma unroll
            for (int j = 0; j < 4; j++)
                ldsm_x4(bf[2*j][0], bf[2*j][1], bf[2*j+1][0], bf[2*j+1][1],
                        b_st + boff[j] + k16 * 2);
            #pragma unroll
            for (int mf = 0; mf < 2; mf++)
                #pragma unroll
                for (int nf = 0; nf < 8; nf++)
                    mma_f16(acc[mf][nf][0], acc[mf][nf][1],
                            acc[mf][nf][2], acc[mf][nf][3],
                            af[mf][0], af[mf][1], af[mf][2], af[mf][3],
                            bf[nf][0], bf[nf][1]);
        }
    }

    #pragma unroll
    for (int mf = 0; mf < 2; mf++) {
        const long row = bm + wy * 32 + mf * 16 + g;
        #pragma unroll
        for (int nf = 0; nf < 8; nf++) {
            const long col = bn + wx * 64 + nf * 8 + t * 2;
            float2 v0 = make_float2(acc[mf][nf][0], acc[mf][nf][1]);
            float2 v1 = make_float2(acc[mf][nf][2], acc[mf][nf][3]);
            if (EPI & 1) {
                const float2 bv = *reinterpret_cast<const float2*>(bias + col);
                v0.x += bv.x; v0.y += bv.y;
                v1.x += bv.x; v1.y += bv.y;
            }
            if (EPI & 2) {
                v0.x = gelu_erf(v0.x); v0.y = gelu_erf(v0.y);
                v1.x = gelu_erf(v1.x); v1.y = gelu_erf(v1.y);
            }
            if (EPI & 4) {
                const float2 r0 = *reinterpret_cast<const float2*>(R + row * N + col);
                const float2 r1 = *reinterpret_cast<const float2*>(R + (row + 8) * N + col);
                v0.x += r0.x; v0.y += r0.y;
                v1.x += r1.x; v1.y += r1.y;
            }
            if (HOUT) {
                __half* C = reinterpret_cast<__half*>(Cv);
                *reinterpret_cast<uint32_t*>(C + row * N + col) = pack_f16x2(v0.x, v0.y);
                *reinterpret_cast<uint32_t*>(C + (row + 8) * N + col) = pack_f16x2(v1.x, v1.y);
            } else {
                float* C = reinterpret_cast<float*>(Cv);
                *reinterpret_cast<float2*>(C + row * N + col) = v0;
                *reinterpret_cast<float2*>(C + (row + 8) * N + col) = v1;
            }
        }
    }
}

// ---------------------------------------------------------------------------
// fp16 flash attention: 128 q-rows/CTA, 8 warps x 16 rows. Q in registers;
// K via ldmatrix (B-frag), V via ldmatrix.trans; P stays in registers.
// ---------------------------------------------------------------------------
#define KVST 72
#define KVBUF (64 * KVST)
#define FK_OFF 0
#define FV_OFF (2 * KVBUF)
#define FLASH_SMEM (4 * KVBUF * 2)      // 36864 bytes

__global__ void __launch_bounds__(256, 2) flash_h(
    const __half* __restrict__ qkv, __half* __restrict__ out)
{
    extern __shared__ __half smh[];
    const uint32_t k_su = smem_u32(smh + FK_OFF);
    const uint32_t v_su = smem_u32(smh + FV_OFF);

    const int tid = threadIdx.x;
    const int lane = tid & 31, warp = tid >> 5;
    const int g = lane >> 2, t = lane & 3;
    const int lm = lane >> 3, lr = lane & 7;
    const int b = blockIdx.y >> 4, h = blockIdx.y & 15;
    const int q0 = blockIdx.x * 128;
    const int m0 = warp * 16;
    const long base = (long)b * SEQ * C3 + h * HD;

    // K ldmatrix lane offsets (keys as B-frag rows)
    uint32_t koff[4];
    #pragma unroll
    for (int j = 0; j < 4; j++)
        koff[j] = (uint32_t)(((j * 16 + ((lane >> 4) & 1) * 8 + (lane & 7)) * KVST
                              + ((lane >> 3) & 1) * 8) * 2);

    // Q fragments from global fp16, 16 regs
    uint32_t qf[4][4];
    {
        const uint32_t* q_lo = reinterpret_cast<const uint32_t*>(
            qkv + base + (long)(q0 + m0 + g) * C3);
        const uint32_t* q_hi = reinterpret_cast<const uint32_t*>(
            qkv + base + (long)(q0 + m0 + g + 8) * C3);
        #pragma unroll
        for (int s = 0; s < 4; s++) {
            qf[s][0] = q_lo[8 * s + t];
            qf[s][1] = q_hi[8 * s + t];
            qf[s][2] = q_lo[8 * s + t + 4];
            qf[s][3] = q_hi[8 * s + t + 4];
        }
    }

    auto issue_kv = [&](int kt, int bf) {
        const long kb = base + (long)(kt * 64) * C3;
        #pragma unroll
        for (int i = 0; i < 2; i++) {
            int id = i * 256 + tid;
            int r = id >> 3, c = (id & 7) << 3;
            cp_async16(k_su + (uint32_t)(bf * KVBUF + r * KVST + c) * 2,
                       qkv + kb + (long)r * C3 + 1024 + c);
        }
        #pragma unroll
        for (int i = 0; i < 2; i++) {
            int id = i * 256 + tid;
            int r = id >> 3, c = (id & 7) << 3;
            cp_async16(v_su + (uint32_t)(bf * KVBUF + r * KVST + c) * 2,
                       qkv + kb + (long)r * C3 + 2048 + c);
        }
        CP_COMMIT;
    };

    float Of[8][4];
    #pragma unroll
    for (int nf = 0; nf < 8; nf++)
        #pragma unroll
        for (int e = 0; e < 4; e++) Of[nf][e] = 0.f;
    float m_[2] = {-1e30f, -1e30f};
    float l_[2] = {0.f, 0.f};
    const float sscale = 0.125f * 1.4426950408889634f;

    issue_kv(0, 0);

    const int NT = SEQ / 64;
    for (int kt = 0; kt < NT; kt++) {
        const int buf = kt & 1;
        __syncthreads();
        if (kt + 1 < NT) { issue_kv(kt + 1, buf ^ 1); cp_wait<1>(); }
        else             { cp_wait<0>(); }
        __syncthreads();

        const uint32_t k_base = k_su + (uint32_t)(buf * KVBUF) * 2;

        // S = Q @ K^T  (K fragments via ldmatrix)
        float Sf[8][4];
        #pragma unroll
        for (int nf = 0; nf < 8; nf++)
            #pragma unroll
            for (int e = 0; e < 4; e++) Sf[nf][e] = 0.f;

        #pragma unroll
        for (int s = 0; s < 4; s++) {
            uint32_t kf[8][2];
            #pragma unroll
            for (int j = 0; j < 4; j++)
                ldsm_x4(kf[2*j][0], kf[2*j][1], kf[2*j+1][0], kf[2*j+1][1],
                        k_base + koff[j] + s * 32);
            #pragma unroll
            for (int nf = 0; nf < 8; nf++)
                mma_f16(Sf[nf][0], Sf[nf][1], Sf[nf][2], Sf[nf][3],
                        qf[s][0], qf[s][1], qf[s][2], qf[s][3],
                        kf[nf][0], kf[nf][1]);
        }
        #pragma unroll
        for (int nf = 0; nf < 8; nf++)
            #pragma unroll
            for (int e = 0; e < 4; e++) Sf[nf][e] *= sscale;

        // Online softmax
        #pragma unroll
        for (int r = 0; r < 2; r++) {
            const int e = r * 2;
            float mx = -1e30f;
            #pragma unroll
            for (int nf = 0; nf < 8; nf++)
                mx = fmaxf(mx, fmaxf(Sf[nf][e], Sf[nf][e + 1]));
            mx = fmaxf(mx, __shfl_xor_sync(0xffffffffu, mx, 1));
            mx = fmaxf(mx, __shfl_xor_sync(0xffffffffu, mx, 2));
            const float nm = fmaxf(m_[r], mx);
            const float corr = exp2f(m_[r] - nm);
            float ps = 0.f;
            #pragma unroll
            for (int nf = 0; nf < 8; nf++) {
                Sf[nf][e]     = exp2f(Sf[nf][e] - nm);
                Sf[nf][e + 1] = exp2f(Sf[nf][e + 1] - nm);
                ps += Sf[nf][e] + Sf[nf][e + 1];
            }
            ps += __shfl_xor_sync(0xffffffffu, ps, 1);
            ps += __shfl_xor_sync(0xffffffffu, ps, 2);
            l_[r] = l_[r] * corr + ps;
            m_[r] = nm;
            #pragma unroll
            for (int nf = 0; nf < 8; nf++) {
                Of[nf][e] *= corr; Of[nf][e + 1] *= corr;
            }
        }

        // O += P @ V
        const uint32_t v_base = v_su + (uint32_t)(buf * KVBUF) * 2;
        #pragma unroll
        for (int s = 0; s < 4; s++) {
            uint32_t pa0 = pack_f16x2(Sf[2*s][0],   Sf[2*s][1]);
            uint32_t pa1 = pack_f16x2(Sf[2*s][2],   Sf[2*s][3]);
            uint32_t pa2 = pack_f16x2(Sf[2*s+1][0], Sf[2*s+1][1]);
            uint32_t pa3 = pack_f16x2(Sf[2*s+1][2], Sf[2*s+1][3]);
            #pragma unroll
            for (int np = 0; np < 4; np++) {
                uint32_t b0a, b1a, b0b, b1b;
                const uint32_t addr = v_base +
                    (uint32_t)((16 * s + (lm & 1) * 8 + lr) * KVST + 16 * np + (lm >> 1) * 8) * 2;
                ldsm_x4_t(b0a, b1a, b0b, b1b, addr);
                mma_f16(Of[2*np][0],   Of[2*np][1],   Of[2*np][2],   Of[2*np][3],
                        pa0, pa1, pa2, pa3, b0a, b1a);
                mma_f16(Of[2*np+1][0], Of[2*np+1][1], Of[2*np+1][2], Of[2*np+1][3],
                        pa0, pa1, pa2, pa3, b0b, b1b);
            }
        }
    }

    // Normalize, write fp16 merged heads
    #pragma unroll
    for (int r = 0; r < 2; r++) {
        const float inv = 1.0f / l_[r];
        const long row = (long)b * SEQ + q0 + m0 + g + r * 8;
        const int e = r * 2;
        #pragma unroll
        for (int nf = 0; nf < 8; nf++) {
            *reinterpret_cast<uint32_t*>(out + row * DIM + h * HD + nf * 8 + 2 * t) =
                pack_f16x2(Of[nf][e] * inv, Of[nf][e + 1] * inv);
        }
    }
}

// ---------------------------------------------------------------------------
// Weight transpose + fp16 convert
// ---------------------------------------------------------------------------
__global__ void __launch_bounds__(256) cvt_T(
    const float* __restrict__ in, __half* __restrict__ out, int Rr, int Cc)
{
    __shared__ float tb[32][33];
    const int c0 = blockIdx.x * 32, r0 = blockIdx.y * 32;
    const int x = threadIdx.x & 31, y = (threadIdx.x >> 5) * 4;
    #pragma unroll
    for (int i = 0; i < 4; i++)
        tb[y + i][x] = in[(long)(r0 + y + i) * Cc + c0 + x];
    __syncthreads();
    #pragma unroll
    for (int i = 0; i < 4; i++)
        out[(long)(c0 + y + i) * Rr + r0 + x] = __float2half(tb[x][y + i]);
}

// ---------------------------------------------------------------------------
// LayerNorm -> fp16
// ---------------------------------------------------------------------------
__global__ void __launch_bounds__(256) ln_h_kernel(
    const float* __restrict__ x, const float* __restrict__ g,
    const float* __restrict__ b, __half* __restrict__ out)
{
    const int row = blockIdx.x;
    const int tid = threadIdx.x;
    float4 v = reinterpret_cast<const float4*>(x + (long)row * DIM)[tid];

    __shared__ float red1[8];
    __shared__ float red2[8];

    float s = v.x + v.y + v.z + v.w;
    #pragma unroll
    for (int off = 16; off; off >>= 1) s += __shfl_xor_sync(0xffffffffu, s, off);
    if ((tid & 31) == 0) red1[tid >> 5] = s;
    __syncthreads();
    float tot = 0.f;
    #pragma unroll
    for (int w = 0; w < 8; w++) tot += red1[w];
    const float mean = tot * (1.0f / DIM);

    float dx = v.x - mean, dy = v.y - mean, dz = v.z - mean, dw = v.w - mean;
    float q = dx * dx + dy * dy + dz * dz + dw * dw;
    #pragma unroll
    for (int off = 16; off; off >>= 1) q += __shfl_xor_sync(0xffffffffu, q, off);
    if ((tid & 31) == 0) red2[tid >> 5] = q;
    __syncthreads();
    float qtot = 0.f;
    #pragma unroll
    for (int w = 0; w < 8; w++) qtot += red2[w];
    const float rstd = rsqrtf(qtot * (1.0f / DIM) + 1e-5f);

    float4 gv = reinterpret_cast<const float4*>(g)[tid];
    float4 bv = reinterpret_cast<const float4*>(b)[tid];
    uint32_t* op = reinterpret_cast<uint32_t*>(out + (long)row * DIM) + 2 * tid;
    op[0] = pack_f16x2(dx * rstd * gv.x + bv.x, dy * rstd * gv.y + bv.y);
    op[1] = pack_f16x2(dz * rstd * gv.z + bv.z, dw * rstd * gv.w + bv.w);
}

// ---------------------------------------------------------------------------
// Launch
// ---------------------------------------------------------------------------
extern "C" void kernel_launch(void* const* d_in, const int* in_sizes, int n_in,
                              void* d_out, int out_size)
{
    const float* x      = (const float*)d_in[0];
    const float* ln1_g  = (const float*)d_in[1];
    const float* ln1_b  = (const float*)d_in[2];
    const float* w_qkv  = (const float*)d_in[3];
    const float* w_proj = (const float*)d_in[4];
    const float* b_proj = (const float*)d_in[5];
    const float* ln2_g  = (const float*)d_in[6];
    const float* ln2_b  = (const float*)d_in[7];
    const float* w1     = (const float*)d_in[8];
    const float* b1     = (const float*)d_in[9];
    const float* w2     = (const float*)d_in[10];
    const float* b2     = (const float*)d_in[11];
    float* out = (float*)d_out;

    float *x1;
    __half *qkvh, *h1, *h2, *attn, *hid, *wqkvT, *wprojT, *w1T, *w2T;
    cudaGetSymbolAddress((void**)&x1,     g_x1);
    cudaGetSymbolAddress((void**)&qkvh,   g_qkvh);
    cudaGetSymbolAddress((void**)&h1,     g_h1);
    cudaGetSymbolAddress((void**)&h2,     g_h2);
    cudaGetSymbolAddress((void**)&attn,   g_attn);
    cudaGetSymbolAddress((void**)&hid,    g_hid);
    cudaGetSymbolAddress((void**)&wqkvT,  g_wqkvT);
    cudaGetSymbolAddress((void**)&wprojT, g_wprojT);
    cudaGetSymbolAddress((void**)&w1T,    g_w1T);
    cudaGetSymbolAddress((void**)&w2T,    g_w2T);

    cudaFuncSetAttribute(mma_gemm_h<0,1>, cudaFuncAttributeMaxDynamicSharedMemorySize, GEMMH_SMEM);
    cudaFuncSetAttribute(mma_gemm_h<5,0>, cudaFuncAttributeMaxDynamicSharedMemorySize, GEMMH_SMEM);
    cudaFuncSetAttribute(mma_gemm_h<3,1>, cudaFuncAttributeMaxDynamicSharedMemorySize, GEMMH_SMEM);
    cudaFuncSetAttribute(flash_h,         cudaFuncAttributeMaxDynamicSharedMemorySize, FLASH_SMEM);

    // Weight transposes -> fp16 k-major [N][K]
    cvt_T<<<dim3(C3 / 32,     DIM / 32),    256>>>(w_qkv,  wqkvT,  DIM,    C3);
    cvt_T<<<dim3(DIM / 32,    DIM / 32),    256>>>(w_proj, wprojT, DIM,    DIM);
    cvt_T<<<dim3(HIDDEN / 32, DIM / 32),    256>>>(w1,     w1T,    DIM,    HIDDEN);
    cvt_T<<<dim3(DIM / 32,    HIDDEN / 32), 256>>>(w2,     w2T,    HIDDEN, DIM);

    // 1) h1 = LN1(x)  (fp16)
    ln_h_kernel<<<TOK, 256>>>(x, ln1_g, ln1_b, h1);

    // 2) qkvh = h1 @ w_qkv  (fp16 out)
    mma_gemm_h<0,1><<<dim3(C3 / 128, TOK / 128), 256, GEMMH_SMEM>>>(
        h1, wqkvT, nullptr, nullptr, qkvh, TOK, C3, DIM);

    // 3) attention (fp16 flash, register P, ldmatrix K/V)
    flash_h<<<dim3(SEQ / 128, BATCH * HEADS), 256, FLASH_SMEM>>>(qkvh, attn);

    // 4) x1 = x + attn @ w_proj + b_proj  (fp32 residual)
    mma_gemm_h<5,0><<<dim3(DIM / 128, TOK / 128), 256, GEMMH_SMEM>>>(
        attn, wprojT, b_proj, x, x1, TOK, DIM, DIM);

    // 5) h2 = LN2(x1)  (fp16)
    ln_h_kernel<<<TOK, 256>>>(x1, ln2_g, ln2_b, h2);

    // 6) hid = gelu(h2 @ w1 + b1)  (fp16 out)
    mma_gemm_h<3,1><<<dim3(HIDDEN / 128, TOK / 128), 256, GEMMH_SMEM>>>(
        h2, w1T, b1, nullptr, hid, TOK, HIDDEN, DIM);

    // 7) out = x1 + hid @ w2 + b2  (fp32 residual)
    mma_gemm_h<5,0><<<dim3(DIM / 128, TOK / 128), 256, GEMMH_SMEM>>>(
        hid, w2T, b2, x1, out, TOK, DIM, HIDDEN);
}